// round 6
// baseline (speedup 1.0000x reference)
#include <cuda_runtime.h>
#include <math.h>
#include <stdint.h>

#define B_   64
#define T_   2000
#define E_   512
#define D_   1024
#define A_   128
#define PAD_ 15
#define TTILE  64
#define NTILES 32          // ceil(2000/64)
#define NCHUNKS 9          // chunk 0 = conv (im2col), 1..8 = memory K
#define CCH  50            // context chunks (2000 = 50*40)
#define CLEN 40

// ---- device scratch (allocation-free rule) ----
__device__ __align__(16) float g_pq[B_ * A_];
__device__ __align__(16) float g_scores[B_ * T_];
__device__ __align__(16) float g_part[B_ * CCH * E_];
__device__ __align__(16) char  g_W8[NCHUNKS * A_ * 128];  // [chunk][a][hi64|lo64]
__device__ float g_sW[A_];

// ---- smem layout (bytes) ----
#define S_AW   0            // 2 x 96 floats
#define S_PQ   768
#define S_V    1280
#define S_SW   1792
#define S_SC   2304         // 2 x 64 floats
#define S_SA   2816         // 2 bufs x 64 floats
#define OFF_A  3328         // 2 bufs x 8192  (64 rows x 128B: hi64|lo64)
#define OFF_B  (OFF_A + 16384)  // 2 bufs x 16384 (128 rows x 128B)
#define SMEM_TOTAL (OFF_B + 32768)   // 52480

// ---------------- PTX helpers ----------------
__device__ __forceinline__ uint32_t smem_u32(const void* p) {
    uint32_t a;
    asm("{ .reg .u64 t; cvta.to.shared.u64 t, %1; cvt.u32.u64 %0, t; }"
        : "=r"(a) : "l"(p));
    return a;
}
__device__ __forceinline__ void cp16(uint32_t dst, const void* src) {
    asm volatile("cp.async.cg.shared.global [%0], [%1], 16;"
                 :: "r"(dst), "l"(src) : "memory");
}
__device__ __forceinline__ void cp_commit() {
    asm volatile("cp.async.commit_group;" ::: "memory");
}
__device__ __forceinline__ void cp_wait0() {
    asm volatile("cp.async.wait_group 0;" ::: "memory");
}
#define LDSM4(R, addr)                                                        \
    asm volatile("ldmatrix.sync.aligned.m8n8.x4.shared.b16 {%0,%1,%2,%3}, [%4];" \
                 : "=r"((R)[0]), "=r"((R)[1]), "=r"((R)[2]), "=r"((R)[3])     \
                 : "r"(addr))
#define MMAI8(acc, A, b0, b1)                                                 \
    asm volatile("mma.sync.aligned.m16n8k32.row.col.s32.s8.s8.s32 "           \
                 "{%0,%1,%2,%3},{%4,%5,%6,%7},{%8,%9},{%0,%1,%2,%3};"         \
                 : "+r"((acc)[0]), "+r"((acc)[1]), "+r"((acc)[2]), "+r"((acc)[3]) \
                 : "r"((A)[0]), "r"((A)[1]), "r"((A)[2]), "r"((A)[3]),        \
                   "r"(b0), "r"(b1))

// exact int->float for |v| < 2^22
__device__ __forceinline__ float itof22(int v) {
    return __int_as_float(0x4B400000 + v) - 12582912.f;
}
#define QMAX 32639.0f

// ---------------------------------------------------------------------------
// prep: per-column (a) quantization of [Wloc | Wm] into int8 hi/lo planes
// ---------------------------------------------------------------------------
__global__ void prep_w8_kernel(const float* __restrict__ Wm,
                               const float* __restrict__ Wloc) {
    int a = blockIdx.x, tid = threadIdx.x;   // 128 threads
    __shared__ float red[128];
    float m = 0.f;
    for (int k = tid; k < 576; k += 128) {
        float w = (k < 64) ? ((k < 62) ? Wloc[a * 62 + k] : 0.f)
                           : Wm[a * E_ + (k - 64)];
        m = fmaxf(m, fabsf(w));
    }
    red[tid] = m;
    __syncthreads();
    for (int off = 64; off; off >>= 1) {
        if (tid < off) red[tid] = fmaxf(red[tid], red[tid + off]);
        __syncthreads();
    }
    float s = fmaxf(red[0], 1e-30f);
    float inv = QMAX / s;
    for (int k = tid; k < 576; k += 128) {
        float w = (k < 64) ? ((k < 62) ? Wloc[a * 62 + k] : 0.f)
                           : Wm[a * E_ + (k - 64)];
        int X = __float2int_rn(w * inv);
        int h = (X + 128) >> 8;
        int l = X - (h << 8);
        int chunk = k >> 6, kc = k & 63;
        g_W8[chunk * 16384 + a * 128 + kc] = (char)h;
        g_W8[chunk * 16384 + a * 128 + 64 + kc] = (char)l;
    }
    if (tid == 0) g_sW[a] = s * (1.f / QMAX);
}

// ---------------------------------------------------------------------------
// pq[b][a] = query[b] . Wq[a]
// ---------------------------------------------------------------------------
__global__ void pq_kernel(const float* __restrict__ query,
                          const float* __restrict__ Wq) {
    int b = blockIdx.x;
    int warp = threadIdx.x >> 5, lane = threadIdx.x & 31;
    const float* q = query + (size_t)b * D_;
    for (int a = warp; a < A_; a += 4) {
        const float* w = Wq + (size_t)a * D_;
        float s = 0.f;
        for (int k = lane; k < D_; k += 32) s += q[k] * w[k];
        #pragma unroll
        for (int off = 16; off; off >>= 1)
            s += __shfl_xor_sync(0xffffffffu, s, off);
        if (lane == 0) g_pq[b * A_ + a] = s;
    }
}

// ---------------------------------------------------------------------------
// int8 quantize one 64-value A row (two threads per row), store swizzled
// ---------------------------------------------------------------------------
__device__ __forceinline__ void quant_store_row(
    const float* xv, unsigned char* abuf, float* sSAslot, int cr, int ch) {
    float m = 0.f;
    #pragma unroll
    for (int i = 0; i < 32; ++i) m = fmaxf(m, fabsf(xv[i]));
    m = fmaxf(m, __shfl_xor_sync(0xffffffffu, m, 1));
    float s = fmaxf(m, 1e-20f);
    float inv = QMAX / s;
    if (ch == 0) sSAslot[cr] = s * (1.f / QMAX);
    uint32_t hw[8], lw[8];
    #pragma unroll
    for (int w8 = 0; w8 < 8; ++w8) {
        uint32_t hv = 0, lv = 0;
        #pragma unroll
        for (int bt = 0; bt < 4; ++bt) {
            int X = __float2int_rn(xv[w8 * 4 + bt] * inv);
            int h = (X + 128) >> 8;
            int l = X - (h << 8);
            hv |= (uint32_t)(h & 255) << (8 * bt);
            lv |= (uint32_t)(l & 255) << (8 * bt);
        }
        hw[w8] = hv;
        lw[w8] = lv;
    }
    unsigned char* base = abuf + cr * 128;
    uint32_t crx = (uint32_t)(cr & 7);
    *(uint4*)(base + ((((uint32_t)(2 * ch + 0)) ^ crx) << 4)) =
        make_uint4(hw[0], hw[1], hw[2], hw[3]);
    *(uint4*)(base + ((((uint32_t)(2 * ch + 1)) ^ crx) << 4)) =
        make_uint4(hw[4], hw[5], hw[6], hw[7]);
    *(uint4*)(base + ((((uint32_t)((4 + 2 * ch) ^ crx)) & 7u) << 4)) =
        make_uint4(lw[0], lw[1], lw[2], lw[3]);
    *(uint4*)(base + ((((uint32_t)((5 + 2 * ch) ^ crx)) & 7u) << 4)) =
        make_uint4(lw[4], lw[5], lw[6], lw[7]);
}

__device__ __forceinline__ void i8_pass(
    int (&acc)[2][8][4], uint32_t curA, uint32_t curB, int aHalf, int bHalf,
    const uint32_t (&aRowB)[2], const uint32_t (&bRowB)[4],
    uint32_t aCk, uint32_t bCk, uint32_t rx) {
    #pragma unroll
    for (int ks = 0; ks < 2; ++ks) {
        uint32_t Af[2][4];
        #pragma unroll
        for (int m = 0; m < 2; ++m)
            LDSM4(Af[m], curA + aRowB[m] +
                         ((((uint32_t)(aHalf + 2 * ks) + aCk) ^ rx) << 4));
        uint32_t Bf[4][4];
        #pragma unroll
        for (int g = 0; g < 4; ++g)
            LDSM4(Bf[g], curB + bRowB[g] +
                         ((((uint32_t)(bHalf + 2 * ks) + bCk) ^ rx) << 4));
        #pragma unroll
        for (int m = 0; m < 2; ++m)
            #pragma unroll
            for (int g = 0; g < 4; ++g) {
                MMAI8(acc[m][2 * g],     Af[m], Bf[g][0], Bf[g][1]);
                MMAI8(acc[m][2 * g + 1], Af[m], Bf[g][2], Bf[g][3]);
            }
    }
}

__device__ __forceinline__ void drain_acc(
    float (&mst)[2][8][4], int (&acc)[2][8][4],
    const float (&sr)[2][2], float passScale) {
    #pragma unroll
    for (int m = 0; m < 2; ++m) {
        float f0 = sr[m][0] * passScale;
        float f1 = sr[m][1] * passScale;
        #pragma unroll
        for (int n = 0; n < 8; ++n) {
            mst[m][n][0] += f0 * itof22(acc[m][n][0]);
            mst[m][n][1] += f0 * itof22(acc[m][n][1]);
            mst[m][n][2] += f1 * itof22(acc[m][n][2]);
            mst[m][n][3] += f1 * itof22(acc[m][n][3]);
            acc[m][n][0] = 0; acc[m][n][1] = 0;
            acc[m][n][2] = 0; acc[m][n][3] = 0;
        }
    }
}

// ---------------------------------------------------------------------------
// scores via int8 IMMA split: D = sA*sW*(65536 HH + 256 (HL+LH) + LL)
// ---------------------------------------------------------------------------
__global__ void __launch_bounds__(128, 2)
scores_i8_kernel(const float* __restrict__ memory,
                 const float* __restrict__ aw,
                 const float* __restrict__ v) {
    extern __shared__ unsigned char smem[];
    const uint32_t sb = smem_u32(smem);
    const int tid = threadIdx.x;
    const int wid = tid >> 5, lid = tid & 31;
    const int b = blockIdx.y;
    const int t0 = blockIdx.x * TTILE;

    float* sAw = (float*)(smem + S_AW);
    float* sPQ = (float*)(smem + S_PQ);
    float* sV  = (float*)(smem + S_V);
    float* sSW = (float*)(smem + S_SW);
    float* sSc = (float*)(smem + S_SC);
    float* sSA = (float*)(smem + S_SA);

    const int warpT = wid >> 1, warpA = wid & 1;
    const int tBase = warpT * 32;
    const int aBase = warpA * 64;

    const int aRowOff = (lid & 7) + ((lid >> 3) & 1) * 8;
    const uint32_t aCk = (uint32_t)(lid >> 4);
    const int bRowOff = (lid & 7) + (lid >> 4) * 8;
    const uint32_t bCk = (uint32_t)((lid >> 3) & 1);
    const uint32_t rx = (uint32_t)(lid & 7);

    const int cr = tid >> 1, ch = tid & 1;

    for (int i = tid; i < TTILE + 2 * PAD_; i += 128) {
        int tg = t0 - PAD_ + i;
        float c0 = 0.f, c1 = 0.f;
        if (tg >= 0 && tg < T_) {
            const float* p = aw + ((size_t)b * T_ + tg) * 2;
            c0 = p[0]; c1 = p[1];
        }
        sAw[i] = c0;
        sAw[96 + i] = c1;
    }
    sPQ[tid] = g_pq[b * A_ + tid];
    sV[tid] = v[tid];
    sSW[tid] = g_sW[tid];
    __syncthreads();

    // -------- prologue: chunk 0 (conv) into buf0 --------
    {
        float xv[32];
        #pragma unroll
        for (int i = 0; i < 32; ++i) {
            int j = ch * 32 + i;
            float x = 0.f;
            if (j < 62) {
                int cx = (j >= 31);
                x = sAw[cx * 96 + cr + (j - cx * 31)];
            }
            xv[i] = x;
        }
        quant_store_row(xv, smem + OFF_A, sSA, cr, ch);
        #pragma unroll
        for (int it = 0; it < 8; ++it) {
            int idx = it * 128 + tid;
            uint32_t row = (uint32_t)(idx >> 3), q = (uint32_t)(idx & 7);
            uint32_t dst = sb + OFF_B + (row << 7) + (((q ^ row) & 7u) << 4);
            cp16(dst, g_W8 + row * 128 + q * 16);
        }
        cp_commit();
        cp_wait0();
    }
    __syncthreads();

    float mst[2][8][4];
    int acc[2][8][4];
    #pragma unroll
    for (int m = 0; m < 2; ++m)
        #pragma unroll
        for (int n = 0; n < 8; ++n)
            #pragma unroll
            for (int e = 0; e < 4; ++e) { mst[m][n][e] = 0.f; acc[m][n][e] = 0; }

    uint32_t aRowB[2], bRowB[4];
    #pragma unroll
    for (int m = 0; m < 2; ++m) aRowB[m] = (uint32_t)(tBase + m * 16 + aRowOff) << 7;
    #pragma unroll
    for (int g = 0; g < 4; ++g) bRowB[g] = (uint32_t)(aBase + g * 16 + bRowOff) << 7;

    for (int c = 0; c < NCHUNKS; ++c) {
        const int cur = c & 1, nxt = (c + 1) & 1;
        const uint32_t curA = sb + OFF_A + (uint32_t)cur * 8192;
        const uint32_t curB = sb + OFF_B + (uint32_t)cur * 16384;
        const bool have_next = (c + 1 < NCHUNKS);

        float xv[32];
        if (have_next) {
            const int kb = c * 64;     // chunk c+1 -> kbase
            const uint32_t nxtB = sb + OFF_B + (uint32_t)nxt * 16384;
            const char* wsrc = g_W8 + (size_t)(c + 1) * 16384;
            #pragma unroll
            for (int it = 0; it < 8; ++it) {
                int idx = it * 128 + tid;
                uint32_t row = (uint32_t)(idx >> 3), q = (uint32_t)(idx & 7);
                uint32_t dst = nxtB + (row << 7) + (((q ^ row) & 7u) << 4);
                cp16(dst, wsrc + row * 128 + q * 16);
            }
            cp_commit();
            int gt = t0 + cr;
            if (gt < T_) {
                const float* src = memory + ((size_t)b * T_ + gt) * E_ + kb + ch * 32;
                #pragma unroll
                for (int j = 0; j < 8; ++j) {
                    float4 f = *(const float4*)(src + j * 4);
                    xv[j * 4 + 0] = f.x; xv[j * 4 + 1] = f.y;
                    xv[j * 4 + 2] = f.z; xv[j * 4 + 3] = f.w;
                }
            } else {
                #pragma unroll
                for (int j = 0; j < 32; ++j) xv[j] = 0.f;
            }
        }

        float sr[2][2];
        {
            const float* sSAc = sSA + cur * 64;
            #pragma unroll
            for (int m = 0; m < 2; ++m) {
                int r = tBase + 16 * m + (lid >> 2);
                sr[m][0] = sSAc[r];
                sr[m][1] = sSAc[r + 8];
            }
        }

        // HH
        i8_pass(acc, curA, curB, 0, 0, aRowB, bRowB, aCk, bCk, rx);
        drain_acc(mst, acc, sr, 65536.f);
        // CROSS: Ah*Bl + Al*Bh (shared accumulator)
        i8_pass(acc, curA, curB, 0, 4, aRowB, bRowB, aCk, bCk, rx);
        i8_pass(acc, curA, curB, 4, 0, aRowB, bRowB, aCk, bCk, rx);
        drain_acc(mst, acc, sr, 256.f);
        // LL
        i8_pass(acc, curA, curB, 4, 4, aRowB, bRowB, aCk, bCk, rx);
        drain_acc(mst, acc, sr, 1.f);

        if (have_next) {
            quant_store_row(xv, smem + OFF_A + nxt * 8192, sSA + nxt * 64, cr, ch);
            cp_wait0();
        }
        __syncthreads();
    }

    // ---- epilogue: score[t] = sum_a v[a]*tanh(sW[a]*mst + pq[a]) ----
    {
        float s[4] = {0.f, 0.f, 0.f, 0.f};
        #pragma unroll
        for (int m = 0; m < 2; ++m) {
            #pragma unroll
            for (int n = 0; n < 8; ++n) {
                int a0 = aBase + n * 8 + (lid & 3) * 2;
                float w0 = sSW[a0], w1 = sSW[a0 + 1];
                float v0 = sV[a0], v1 = sV[a0 + 1];
                float q0 = sPQ[a0], q1 = sPQ[a0 + 1];
                s[2 * m]     += v0 * tanhf(mst[m][n][0] * w0 + q0)
                              + v1 * tanhf(mst[m][n][1] * w1 + q1);
                s[2 * m + 1] += v0 * tanhf(mst[m][n][2] * w0 + q0)
                              + v1 * tanhf(mst[m][n][3] * w1 + q1);
            }
        }
        #pragma unroll
        for (int off = 1; off < 4; off <<= 1) {
            #pragma unroll
            for (int i = 0; i < 4; ++i)
                s[i] += __shfl_xor_sync(0xffffffffu, s[i], off);
        }
        if ((lid & 3) == 0) {
            int r = tBase + (lid >> 2);
            sSc[warpA * 64 + r]      = s[0];
            sSc[warpA * 64 + r + 8]  = s[1];
            sSc[warpA * 64 + r + 16] = s[2];
            sSc[warpA * 64 + r + 24] = s[3];
        }
    }
    __syncthreads();
    if (tid < TTILE) {
        int gt = t0 + tid;
        if (gt < T_) g_scores[b * T_ + gt] = sSc[tid] + sSc[64 + tid];
    }
}

// ---------------------------------------------------------------------------
// softmax over T per batch row (512 threads, shuffle reductions)
// ---------------------------------------------------------------------------
__global__ void softmax_kernel(float* __restrict__ align_out) {
    __shared__ float buf[T_];
    __shared__ float red[16];
    int b = blockIdx.x, tid = threadIdx.x;
    int wid = tid >> 5, lane = tid & 31;
    float mx = -1e30f;
    for (int t = tid; t < T_; t += 512) {
        float s = g_scores[b * T_ + t];
        buf[t] = s;
        mx = fmaxf(mx, s);
    }
    #pragma unroll
    for (int off = 16; off; off >>= 1)
        mx = fmaxf(mx, __shfl_xor_sync(0xffffffffu, mx, off));
    if (lane == 0) red[wid] = mx;
    __syncthreads();
    if (wid == 0) {
        float m2 = (lane < 16) ? red[lane] : -1e30f;
        #pragma unroll
        for (int off = 8; off; off >>= 1)
            m2 = fmaxf(m2, __shfl_xor_sync(0xffffffffu, m2, off));
        if (lane == 0) red[0] = m2;
    }
    __syncthreads();
    mx = red[0];
    __syncthreads();
    float sum = 0.f;
    for (int t = tid; t < T_; t += 512) {
        float e = __expf(buf[t] - mx);
        buf[t] = e;
        sum += e;
    }
    #pragma unroll
    for (int off = 16; off; off >>= 1)
        sum += __shfl_xor_sync(0xffffffffu, sum, off);
    if (lane == 0) red[wid] = sum;
    __syncthreads();
    if (wid == 0) {
        float s2 = (lane < 16) ? red[lane] : 0.f;
        #pragma unroll
        for (int off = 8; off; off >>= 1)
            s2 += __shfl_xor_sync(0xffffffffu, s2, off);
        if (lane == 0) red[0] = s2;
    }
    __syncthreads();
    float inv = 1.f / red[0];
    for (int t = tid; t < T_; t += 512) align_out[b * T_ + t] = buf[t] * inv;
}

// ---------------------------------------------------------------------------
// context partials: 50 chunks of 40 (deterministic, no atomics)
// ---------------------------------------------------------------------------
__global__ void ctx_part_kernel(const float* __restrict__ memory,
                                const float* __restrict__ aligns) {
    int chunk = blockIdx.x, b = blockIdx.y, tid = threadIdx.x;  // 128 threads
    __shared__ float sa[CLEN];
    const float* al = aligns + (size_t)b * T_ + chunk * CLEN;
    if (tid < CLEN) sa[tid] = al[tid];
    __syncthreads();
    const float* mp = memory + ((size_t)b * T_ + (size_t)chunk * CLEN) * E_ + tid * 4;
    float4 acc0 = make_float4(0.f, 0.f, 0.f, 0.f);
    float4 acc1 = make_float4(0.f, 0.f, 0.f, 0.f);
    #pragma unroll 4
    for (int tt = 0; tt < CLEN; tt += 2) {
        float a0 = sa[tt], a1 = sa[tt + 1];
        float4 m0 = *(const float4*)mp;
        float4 m1 = *(const float4*)(mp + E_);
        mp += 2 * E_;
        acc0.x += a0 * m0.x; acc0.y += a0 * m0.y;
        acc0.z += a0 * m0.z; acc0.w += a0 * m0.w;
        acc1.x += a1 * m1.x; acc1.y += a1 * m1.y;
        acc1.z += a1 * m1.z; acc1.w += a1 * m1.w;
    }
    acc0.x += acc1.x; acc0.y += acc1.y; acc0.z += acc1.z; acc0.w += acc1.w;
    *((float4*)(g_part + ((size_t)b * CCH + chunk) * E_) + tid) = acc0;
}

__global__ void ctx_reduce_kernel(float* __restrict__ ctx_out) {
    int b = blockIdx.x, e = threadIdx.x;  // 512 threads
    float s = 0.f;
    #pragma unroll
    for (int c = 0; c < CCH; ++c)
        s += g_part[((size_t)b * CCH + c) * E_ + e];
    ctx_out[b * E_ + e] = s;
}

// ---------------------------------------------------------------------------
extern "C" void kernel_launch(void* const* d_in, const int* in_sizes, int n_in,
                              void* d_out, int out_size) {
    const float* query  = (const float*)d_in[0];  // [64,1024]
    const float* memory = (const float*)d_in[1];  // [64,2000,512]
    const float* aw     = (const float*)d_in[2];  // [64,2000,2]
    const float* Wq     = (const float*)d_in[3];  // [128,1024]
    const float* Wm     = (const float*)d_in[4];  // [128,512]
    const float* Wloc   = (const float*)d_in[5];  // [128,2,31]
    const float* v      = (const float*)d_in[6];  // [128]

    float* ctx = (float*)d_out;                   // [64,512]
    float* aligns = ctx + B_ * E_;                // [64,2000]

    cudaFuncSetAttribute(scores_i8_kernel,
                         cudaFuncAttributeMaxDynamicSharedMemorySize, SMEM_TOTAL);

    prep_w8_kernel<<<A_, 128>>>(Wm, Wloc);
    pq_kernel<<<B_, 128>>>(query, Wq);
    scores_i8_kernel<<<dim3(NTILES, B_), 128, SMEM_TOTAL>>>(memory, aw, v);
    softmax_kernel<<<B_, 512>>>(aligns);
    ctx_part_kernel<<<dim3(CCH, B_), 128>>>(memory, aligns);
    ctx_reduce_kernel<<<B_, 512>>>(ctx);
}

// round 7
// speedup vs baseline: 2.5403x; 2.5403x over previous
#include <cuda_runtime.h>
#include <cuda_fp16.h>
#include <math.h>
#include <stdint.h>

#define B_   64
#define T_   2000
#define E_   512
#define D_   1024
#define A_   128
#define PAD_ 15
#define TTILE  64
#define NTILES 32          // ceil(2000/64)
#define NCHUNKS 9          // chunk 0 = conv (im2col), 1..8 = memory K

// ---- device scratch (allocation-free rule) ----
__device__ __align__(16) float  g_pq[B_ * A_];
__device__ __align__(16) float  g_scores[B_ * T_];
__device__ __align__(16) float  g_cpart[B_ * NTILES * E_];
__device__ __align__(16) float2 g_mtl[B_ * NTILES];
__device__ __align__(16) __half g_WmH[A_ * E_], g_WmL[A_ * E_];
__device__ __align__(16) __half g_WlocH[A_ * 64], g_WlocL[A_ * 64];

// ---- smem layout (bytes) ----
#define S_AW   0            // 2 x 96 floats = 768
#define S_PQ   768          // 128 floats
#define S_V    1280         // 128 floats
#define S_SC   1792         // 2 x 64 floats = 512
#define S_BUF  2304
#define OFF_A  S_BUF        // 2 bufs x 16384 (AH 8192 + AL 8192), 64 rows x 128B
#define OFF_B  (S_BUF + 32768)  // 2 bufs x 32768 (BH 16384 + BL 16384)
#define S_FIN  (S_BUF + 32768 + 65536)   // 64 floats (final tile scores)
#define S_W    (S_FIN + 256)             // 64 floats (exp weights)
#define SMEM_TOTAL (S_W + 256)           // 101120

// ---------------- PTX helpers ----------------
__device__ __forceinline__ uint32_t smem_u32(const void* p) {
    uint32_t a;
    asm("{ .reg .u64 t; cvta.to.shared.u64 t, %1; cvt.u32.u64 %0, t; }"
        : "=r"(a) : "l"(p));
    return a;
}
__device__ __forceinline__ void cp16(uint32_t dst, const void* src) {
    asm volatile("cp.async.cg.shared.global [%0], [%1], 16;"
                 :: "r"(dst), "l"(src) : "memory");
}
__device__ __forceinline__ void cp_commit() {
    asm volatile("cp.async.commit_group;" ::: "memory");
}
__device__ __forceinline__ void cp_wait0() {
    asm volatile("cp.async.wait_group 0;" ::: "memory");
}
#define LDSM4(R, addr)                                                        \
    asm volatile("ldmatrix.sync.aligned.m8n8.x4.shared.b16 {%0,%1,%2,%3}, [%4];" \
                 : "=r"((R)[0]), "=r"((R)[1]), "=r"((R)[2]), "=r"((R)[3])     \
                 : "r"(addr))
#define MMA16816(acc, Af, b0, b1)                                             \
    asm volatile("mma.sync.aligned.m16n8k16.row.col.f32.f16.f16.f32 "         \
                 "{%0,%1,%2,%3},{%4,%5,%6,%7},{%8,%9},{%0,%1,%2,%3};"         \
                 : "+f"((acc)[0]), "+f"((acc)[1]), "+f"((acc)[2]), "+f"((acc)[3]) \
                 : "r"((Af)[0]), "r"((Af)[1]), "r"((Af)[2]), "r"((Af)[3]),    \
                   "r"(b0), "r"(b1))

__device__ __forceinline__ void split2(float x, float y,
                                       uint32_t& hi, uint32_t& lo) {
    __half hx = __float2half_rn(x), hy = __float2half_rn(y);
    __half lx = __float2half_rn(x - __half2float(hx));
    __half ly = __float2half_rn(y - __half2float(hy));
    __half2 H = __halves2half2(hx, hy), L = __halves2half2(lx, ly);
    hi = *(uint32_t*)&H;
    lo = *(uint32_t*)&L;
}

// ---------------------------------------------------------------------------
// prep: split Wm / Wloc into fp16 hi/lo
// ---------------------------------------------------------------------------
__global__ void prep_kernel(const float* __restrict__ Wm,
                            const float* __restrict__ Wloc) {
    int idx = blockIdx.x * 256 + threadIdx.x;    // grid 256 -> 65536
    float x = Wm[idx];
    __half h = __float2half_rn(x);
    __half l = __float2half_rn(x - __half2float(h));
    g_WmH[idx] = h;
    g_WmL[idx] = l;
    if (idx < A_ * 64) {
        int j = idx & 63;
        float w = (j < 62) ? Wloc[(idx >> 6) * 62 + j] : 0.f;
        __half wh = __float2half_rn(w);
        __half wl = __float2half_rn(w - __half2float(wh));
        g_WlocH[idx] = wh;
        g_WlocL[idx] = wl;
    }
}

// ---------------------------------------------------------------------------
// pq[b][a] = query[b] . Wq[a]
// ---------------------------------------------------------------------------
__global__ void pq_kernel(const float* __restrict__ query,
                          const float* __restrict__ Wq) {
    int b = blockIdx.x;
    int warp = threadIdx.x >> 5, lane = threadIdx.x & 31;
    const float* q = query + (size_t)b * D_;
    for (int a = warp; a < A_; a += 4) {
        const float* w = Wq + (size_t)a * D_;
        float s = 0.f;
        for (int k = lane; k < D_; k += 32) s += q[k] * w[k];
        #pragma unroll
        for (int off = 16; off; off >>= 1)
            s += __shfl_xor_sync(0xffffffffu, s, off);
        if (lane == 0) g_pq[b * A_ + a] = s;
    }
}

// ---------------------------------------------------------------------------
// fused: scores (fp16-split HMMA) + tile-local softmax partial + ctx partial
// 64t x 128a tile, 128 threads, 2 CTAs/SM.
// ---------------------------------------------------------------------------
__global__ void __launch_bounds__(128, 2)
scores_fused_kernel(const float* __restrict__ memory,
                    const float* __restrict__ aw,
                    const float* __restrict__ v) {
    extern __shared__ unsigned char smem[];
    const uint32_t sb = smem_u32(smem);
    const int tid = threadIdx.x;
    const int wid = tid >> 5, lid = tid & 31;
    const int b = blockIdx.y;
    const int tile = blockIdx.x;
    const int t0 = tile * TTILE;

    float* sAw  = (float*)(smem + S_AW);     // [2][96]
    float* sPQ  = (float*)(smem + S_PQ);
    float* sV   = (float*)(smem + S_V);
    float* sSc  = (float*)(smem + S_SC);     // [2][64]
    float* sFin = (float*)(smem + S_FIN);    // [64]
    float* sW   = (float*)(smem + S_W);      // [64]

    const int warpT = wid >> 1, warpA = wid & 1;
    const int tBase = warpT * 32;
    const int aBase = warpA * 64;

    const int aRowOff = (lid & 7) + ((lid >> 3) & 1) * 8;
    const uint32_t aCk = (uint32_t)(lid >> 4);
    const int bRowOff = (lid & 7) + (lid >> 4) * 8;
    const uint32_t bCk = (uint32_t)((lid >> 3) & 1);
    const uint32_t rx = (uint32_t)(lid & 7);

    const int cr = tid >> 1, ch = tid & 1;
    const uint32_t crx = (uint32_t)(cr & 7);

    for (int i = tid; i < TTILE + 2 * PAD_; i += 128) {
        int tg = t0 - PAD_ + i;
        float c0 = 0.f, c1 = 0.f;
        if (tg >= 0 && tg < T_) {
            const float* p = aw + ((size_t)b * T_ + tg) * 2;
            c0 = p[0]; c1 = p[1];
        }
        sAw[i] = c0;
        sAw[96 + i] = c1;
    }
    sPQ[tid] = g_pq[b * A_ + tid];
    sV[tid] = v[tid];
    __syncthreads();

    // -------- prologue: chunk 0 (conv) --------
    {
        unsigned char* abuf = smem + OFF_A;   // buffer 0
        float xv[8];
        #pragma unroll
        for (int j2 = 0; j2 < 4; ++j2) {
            #pragma unroll
            for (int e = 0; e < 8; ++e) {
                int j = ch * 32 + j2 * 8 + e;
                float x = 0.f;
                if (j < 62) {
                    int c = (j >= 31);
                    x = sAw[c * 96 + cr + (j - c * 31)];
                }
                xv[e] = x;
            }
            uint4 H, L;
            split2(xv[0], xv[1], H.x, L.x);
            split2(xv[2], xv[3], H.y, L.y);
            split2(xv[4], xv[5], H.z, L.z);
            split2(xv[6], xv[7], H.w, L.w);
            uint32_t c = (uint32_t)(ch * 4 + j2);
            uint32_t dst = (uint32_t)(cr << 7) + (((c ^ crx) & 7u) << 4);
            *(uint4*)(abuf + dst) = H;
            *(uint4*)(abuf + 8192 + dst) = L;
        }
        #pragma unroll
        for (int it = 0; it < 8; ++it) {
            int idx = it * 128 + tid;
            uint32_t row = (uint32_t)(idx >> 3), q = (uint32_t)(idx & 7);
            uint32_t dst = sb + OFF_B + (row << 7) + (((q ^ row) & 7u) << 4);
            cp16(dst, g_WlocH + row * 64 + q * 8);
            cp16(dst + 16384, g_WlocL + row * 64 + q * 8);
        }
        cp_commit();
        cp_wait0();
    }
    __syncthreads();

    float acc[2][8][4];
    #pragma unroll
    for (int m = 0; m < 2; ++m)
        #pragma unroll
        for (int n = 0; n < 8; ++n)
            #pragma unroll
            for (int e = 0; e < 4; ++e) acc[m][n][e] = 0.f;

    uint32_t aRowB[2], bRowB[4];
    #pragma unroll
    for (int m = 0; m < 2; ++m) aRowB[m] = (uint32_t)(tBase + m * 16 + aRowOff) << 7;
    #pragma unroll
    for (int g = 0; g < 4; ++g) bRowB[g] = (uint32_t)(aBase + g * 16 + bRowOff) << 7;

    for (int c = 0; c < NCHUNKS; ++c) {
        const uint32_t curA = sb + OFF_A + (uint32_t)(c & 1) * 16384;
        const uint32_t curB = sb + OFF_B + (uint32_t)(c & 1) * 32768;
        const bool have_next = (c + 1 < NCHUNKS);

        float4 a8[8];
        if (have_next) {
            const int kb = c * 64;   // chunk c+1 -> kbase = c*64
            const uint32_t nxtB = sb + OFF_B + (uint32_t)((c + 1) & 1) * 32768;
            const __half* WH = g_WmH + kb;
            const __half* WL = g_WmL + kb;
            #pragma unroll
            for (int it = 0; it < 8; ++it) {
                int idx = it * 128 + tid;
                uint32_t row = (uint32_t)(idx >> 3), q = (uint32_t)(idx & 7);
                uint32_t dst = nxtB + (row << 7) + (((q ^ row) & 7u) << 4);
                cp16(dst, WH + (size_t)row * E_ + q * 8);
                cp16(dst + 16384, WL + (size_t)row * E_ + q * 8);
            }
            cp_commit();
            int gt = t0 + cr;
            if (gt < T_) {
                const float* src = memory + ((size_t)b * T_ + gt) * E_ + kb + ch * 32;
                #pragma unroll
                for (int j = 0; j < 8; ++j) a8[j] = *(const float4*)(src + j * 4);
            } else {
                #pragma unroll
                for (int j = 0; j < 8; ++j) a8[j] = make_float4(0.f, 0.f, 0.f, 0.f);
            }
        }

        // ---- MMA over current chunk ----
        #pragma unroll
        for (int ks = 0; ks < 4; ++ks) {
            uint32_t ah[2][4], al[2][4];
            #pragma unroll
            for (int m = 0; m < 2; ++m) {
                uint32_t ad = curA + aRowB[m] +
                              ((((uint32_t)(2 * ks) + aCk) ^ rx) << 4);
                LDSM4(ah[m], ad);
                LDSM4(al[m], ad + 8192);
            }
            uint32_t bh[4][4], bl[4][4];
            #pragma unroll
            for (int g = 0; g < 4; ++g) {
                uint32_t bd = curB + bRowB[g] +
                              ((((uint32_t)(2 * ks) + bCk) ^ rx) << 4);
                LDSM4(bh[g], bd);
                LDSM4(bl[g], bd + 16384);
            }
            #pragma unroll
            for (int m = 0; m < 2; ++m) {
                #pragma unroll
                for (int g = 0; g < 4; ++g) {
                    MMA16816(acc[m][2 * g],     ah[m], bh[g][0], bh[g][1]);
                    MMA16816(acc[m][2 * g + 1], ah[m], bh[g][2], bh[g][3]);
                    MMA16816(acc[m][2 * g],     ah[m], bl[g][0], bl[g][1]);
                    MMA16816(acc[m][2 * g + 1], ah[m], bl[g][2], bl[g][3]);
                    MMA16816(acc[m][2 * g],     al[m], bh[g][0], bh[g][1]);
                    MMA16816(acc[m][2 * g + 1], al[m], bh[g][2], bh[g][3]);
                }
            }
        }

        if (have_next) {
            unsigned char* nb = smem + OFF_A + ((c + 1) & 1) * 16384;
            #pragma unroll
            for (int j2 = 0; j2 < 4; ++j2) {
                float4 x = a8[2 * j2], y = a8[2 * j2 + 1];
                uint4 H, L;
                split2(x.x, x.y, H.x, L.x);
                split2(x.z, x.w, H.y, L.y);
                split2(y.x, y.y, H.z, L.z);
                split2(y.z, y.w, H.w, L.w);
                uint32_t cc = (uint32_t)(ch * 4 + j2);
                uint32_t dst = (uint32_t)(cr << 7) + (((cc ^ crx) & 7u) << 4);
                *(uint4*)(nb + dst) = H;
                *(uint4*)(nb + 8192 + dst) = L;
            }
            cp_wait0();
        }
        __syncthreads();
    }

    // ---- scores: s[t] = sum_a v[a]*tanh(acc + pq[a]) ----
    {
        float s[4] = {0.f, 0.f, 0.f, 0.f};
        #pragma unroll
        for (int m = 0; m < 2; ++m) {
            #pragma unroll
            for (int n = 0; n < 8; ++n) {
                int a0 = aBase + n * 8 + (lid & 3) * 2;
                float v0 = sV[a0], v1 = sV[a0 + 1];
                float q0 = sPQ[a0], q1 = sPQ[a0 + 1];
                s[2 * m]     += v0 * tanhf(acc[m][n][0] + q0)
                              + v1 * tanhf(acc[m][n][1] + q1);
                s[2 * m + 1] += v0 * tanhf(acc[m][n][2] + q0)
                              + v1 * tanhf(acc[m][n][3] + q1);
            }
        }
        #pragma unroll
        for (int off = 1; off < 4; off <<= 1) {
            #pragma unroll
            for (int i = 0; i < 4; ++i)
                s[i] += __shfl_xor_sync(0xffffffffu, s[i], off);
        }
        if ((lid & 3) == 0) {
            int r = tBase + (lid >> 2);
            sSc[warpA * 64 + r]      = s[0];
            sSc[warpA * 64 + r + 8]  = s[1];
            sSc[warpA * 64 + r + 16] = s[2];
            sSc[warpA * 64 + r + 24] = s[3];
        }
    }
    __syncthreads();

    // ---- tile softmax partial ----
    if (tid < TTILE) {
        int gt = t0 + tid;
        float sf = sSc[tid] + sSc[64 + tid];
        bool valid = gt < T_;
        if (valid) g_scores[b * T_ + gt] = sf;
        sFin[tid] = valid ? sf : -1e30f;
    }
    __syncthreads();
    if (wid == 0) {
        float s0 = sFin[lid], s1 = sFin[lid + 32];
        float m = fmaxf(s0, s1);
        #pragma unroll
        for (int off = 16; off; off >>= 1)
            m = fmaxf(m, __shfl_xor_sync(0xffffffffu, m, off));
        float w0 = __expf(s0 - m), w1 = __expf(s1 - m);
        float l = w0 + w1;
        #pragma unroll
        for (int off = 16; off; off >>= 1)
            l += __shfl_xor_sync(0xffffffffu, l, off);
        sW[lid] = w0;
        sW[lid + 32] = w1;
        if (lid == 0) g_mtl[b * NTILES + tile] = make_float2(m, l);
    }
    __syncthreads();

    // ---- ctx partial: cpart[e] = sum_t w[t] * memory[b, t0+t, e] (L2-warm) ----
    {
        const int tmax = min(TTILE, T_ - t0);
        const float* mrow = memory + ((size_t)b * T_ + t0) * E_ + tid * 4;
        float4 acc0 = make_float4(0.f, 0.f, 0.f, 0.f);
        float4 acc1 = make_float4(0.f, 0.f, 0.f, 0.f);
        int t = 0;
        for (; t + 2 <= tmax; t += 2) {
            float w0 = sW[t], w1 = sW[t + 1];
            float4 m0 = *(const float4*)(mrow);
            float4 m1 = *(const float4*)(mrow + E_);
            mrow += 2 * E_;
            acc0.x += w0 * m0.x; acc0.y += w0 * m0.y;
            acc0.z += w0 * m0.z; acc0.w += w0 * m0.w;
            acc1.x += w1 * m1.x; acc1.y += w1 * m1.y;
            acc1.z += w1 * m1.z; acc1.w += w1 * m1.w;
        }
        if (t < tmax) {
            float w0 = sW[t];
            float4 m0 = *(const float4*)(mrow);
            acc0.x += w0 * m0.x; acc0.y += w0 * m0.y;
            acc0.z += w0 * m0.z; acc0.w += w0 * m0.w;
        }
        acc0.x += acc1.x; acc0.y += acc1.y;
        acc0.z += acc1.z; acc0.w += acc1.w;
        *((float4*)(g_cpart + ((size_t)b * NTILES + tile) * E_) + tid) = acc0;
    }
}

// ---------------------------------------------------------------------------
// combine: global softmax over tiles -> context + alignments
// ---------------------------------------------------------------------------
__global__ void combine_kernel(float* __restrict__ ctx_out,
                               float* __restrict__ align_out) {
    __shared__ float fac[NTILES];
    __shared__ float sML[2];
    int b = blockIdx.x, tid = threadIdx.x;  // 512 threads
    if (tid < NTILES) {
        float2 ml = g_mtl[b * NTILES + tid];
        float M = ml.x;
        #pragma unroll
        for (int off = 16; off; off >>= 1)
            M = fmaxf(M, __shfl_xor_sync(0xffffffffu, M, off));
        float f = __expf(ml.x - M);
        float L = ml.y * f;
        #pragma unroll
        for (int off = 16; off; off >>= 1)
            L += __shfl_xor_sync(0xffffffffu, L, off);
        fac[tid] = f;
        if (tid == 0) { sML[0] = M; sML[1] = L; }
    }
    __syncthreads();
    float M = sML[0];
    float invL = 1.f / sML[1];

    float s = 0.f;
    #pragma unroll
    for (int i = 0; i < NTILES; ++i)
        s += g_cpart[((size_t)b * NTILES + i) * E_ + tid] * fac[i];
    ctx_out[b * E_ + tid] = s * invL;

    for (int t = tid; t < T_; t += 512)
        align_out[b * T_ + t] = __expf(g_scores[b * T_ + t] - M) * invL;
}

// ---------------------------------------------------------------------------
extern "C" void kernel_launch(void* const* d_in, const int* in_sizes, int n_in,
                              void* d_out, int out_size) {
    const float* query  = (const float*)d_in[0];  // [64,1024]
    const float* memory = (const float*)d_in[1];  // [64,2000,512]
    const float* aw     = (const float*)d_in[2];  // [64,2000,2]
    const float* Wq     = (const float*)d_in[3];  // [128,1024]
    const float* Wm     = (const float*)d_in[4];  // [128,512]
    const float* Wloc   = (const float*)d_in[5];  // [128,2,31]
    const float* v      = (const float*)d_in[6];  // [128]

    float* ctx = (float*)d_out;                   // [64,512]
    float* aligns = ctx + B_ * E_;                // [64,2000]

    cudaFuncSetAttribute(scores_fused_kernel,
                         cudaFuncAttributeMaxDynamicSharedMemorySize, SMEM_TOTAL);

    prep_kernel<<<256, 256>>>(Wm, Wloc);
    pq_kernel<<<B_, 128>>>(query, Wq);
    scores_fused_kernel<<<dim3(NTILES, B_), 128, SMEM_TOTAL>>>(memory, aw, v);
    combine_kernel<<<B_, 512>>>(ctx, aligns);
}

// round 8
// speedup vs baseline: 2.5753x; 1.0138x over previous
#include <cuda_runtime.h>
#include <cuda_fp16.h>
#include <math.h>
#include <stdint.h>

#define B_   64
#define T_   2000
#define E_   512
#define D_   1024
#define A_   128
#define PAD_ 15
#define TTILE  64
#define NTILES 32          // ceil(2000/64)
#define NCHUNKS 9          // chunk 0 = conv (im2col), 1..8 = memory K

// ---- device scratch (allocation-free rule) ----
__device__ __align__(16) float  g_pq[B_ * A_];
__device__ __align__(16) float  g_scores[B_ * T_];
__device__ __align__(16) float  g_cpart[B_ * NTILES * E_];
__device__ __align__(16) float2 g_mtl[B_ * NTILES];
__device__ __align__(16) __half g_WmH[A_ * E_], g_WmL[A_ * E_];
__device__ __align__(16) __half g_WlocH[A_ * 64], g_WlocL[A_ * 64];

// ---- smem layout (bytes) ----
#define S_AW   0            // 2 x 96 floats = 768
#define S_PQ   768          // 128 floats
#define S_V    1280         // 128 floats
#define S_SC   1792         // 2 x 64 floats = 512
#define S_BUF  2304
#define OFF_A  S_BUF        // 2 bufs x 16384 (AH 8192 + AL 8192), 64 rows x 128B
#define OFF_B  (S_BUF + 32768)  // 2 bufs x 32768 (BH 16384 + BL 16384)
#define S_FIN  (S_BUF + 32768 + 65536)   // 64 floats (final tile scores)
#define S_W    (S_FIN + 256)             // 64 floats (exp weights)
#define SMEM_TOTAL (S_W + 256)           // 101120

// ---------------- PTX helpers ----------------
__device__ __forceinline__ uint32_t smem_u32(const void* p) {
    uint32_t a;
    asm("{ .reg .u64 t; cvta.to.shared.u64 t, %1; cvt.u32.u64 %0, t; }"
        : "=r"(a) : "l"(p));
    return a;
}
__device__ __forceinline__ void cp16(uint32_t dst, const void* src) {
    asm volatile("cp.async.cg.shared.global [%0], [%1], 16;"
                 :: "r"(dst), "l"(src) : "memory");
}
__device__ __forceinline__ void cp_commit() {
    asm volatile("cp.async.commit_group;" ::: "memory");
}
__device__ __forceinline__ void cp_wait0() {
    asm volatile("cp.async.wait_group 0;" ::: "memory");
}
#define LDSM4(R, addr)                                                        \
    asm volatile("ldmatrix.sync.aligned.m8n8.x4.shared.b16 {%0,%1,%2,%3}, [%4];" \
                 : "=r"((R)[0]), "=r"((R)[1]), "=r"((R)[2]), "=r"((R)[3])     \
                 : "r"(addr))
#define MMA16816(acc, Af, b0, b1)                                             \
    asm volatile("mma.sync.aligned.m16n8k16.row.col.f32.f16.f16.f32 "         \
                 "{%0,%1,%2,%3},{%4,%5,%6,%7},{%8,%9},{%0,%1,%2,%3};"         \
                 : "+f"((acc)[0]), "+f"((acc)[1]), "+f"((acc)[2]), "+f"((acc)[3]) \
                 : "r"((Af)[0]), "r"((Af)[1]), "r"((Af)[2]), "r"((Af)[3]),    \
                   "r"(b0), "r"(b1))

__device__ __forceinline__ void split2(float x, float y,
                                       uint32_t& hi, uint32_t& lo) {
    __half hx = __float2half_rn(x), hy = __float2half_rn(y);
    __half lx = __float2half_rn(x - __half2float(hx));
    __half ly = __float2half_rn(y - __half2float(hy));
    __half2 H = __halves2half2(hx, hy), L = __halves2half2(lx, ly);
    hi = *(uint32_t*)&H;
    lo = *(uint32_t*)&L;
}

// ---------------------------------------------------------------------------
// prep: split Wm / Wloc into fp16 hi/lo
// ---------------------------------------------------------------------------
__global__ void prep_kernel(const float* __restrict__ Wm,
                            const float* __restrict__ Wloc) {
    int idx = blockIdx.x * 256 + threadIdx.x;    // grid 256 -> 65536
    float x = Wm[idx];
    __half h = __float2half_rn(x);
    __half l = __float2half_rn(x - __half2float(h));
    g_WmH[idx] = h;
    g_WmL[idx] = l;
    if (idx < A_ * 64) {
        int j = idx & 63;
        float w = (j < 62) ? Wloc[(idx >> 6) * 62 + j] : 0.f;
        __half wh = __float2half_rn(w);
        __half wl = __float2half_rn(w - __half2float(wh));
        g_WlocH[idx] = wh;
        g_WlocL[idx] = wl;
    }
}

// ---------------------------------------------------------------------------
// pq[b][a] = query[b] . Wq[a]
// ---------------------------------------------------------------------------
__global__ void pq_kernel(const float* __restrict__ query,
                          const float* __restrict__ Wq) {
    int b = blockIdx.x;
    int warp = threadIdx.x >> 5, lane = threadIdx.x & 31;
    const float* q = query + (size_t)b * D_;
    for (int a = warp; a < A_; a += 4) {
        const float* w = Wq + (size_t)a * D_;
        float s = 0.f;
        for (int k = lane; k < D_; k += 32) s += q[k] * w[k];
        #pragma unroll
        for (int off = 16; off; off >>= 1)
            s += __shfl_xor_sync(0xffffffffu, s, off);
        if (lane == 0) g_pq[b * A_ + a] = s;
    }
}

// ---------------------------------------------------------------------------
// fused: scores (fp16-split HMMA) + tile-local softmax partial + ctx partial
// 64t x 128a tile, 128 threads, 2 CTAs/SM.
// ---------------------------------------------------------------------------
__global__ void __launch_bounds__(128, 2)
scores_fused_kernel(const float* __restrict__ memory,
                    const float* __restrict__ aw,
                    const float* __restrict__ v) {
    extern __shared__ unsigned char smem[];
    const uint32_t sb = smem_u32(smem);
    const int tid = threadIdx.x;
    const int wid = tid >> 5, lid = tid & 31;
    const int b = blockIdx.y;
    const int tile = blockIdx.x;
    const int t0 = tile * TTILE;

    float* sAw  = (float*)(smem + S_AW);     // [2][96]
    float* sPQ  = (float*)(smem + S_PQ);
    float* sV   = (float*)(smem + S_V);
    float* sSc  = (float*)(smem + S_SC);     // [2][64]
    float* sFin = (float*)(smem + S_FIN);    // [64]
    float* sW   = (float*)(smem + S_W);      // [64]

    const int warpT = wid >> 1, warpA = wid & 1;
    const int tBase = warpT * 32;
    const int aBase = warpA * 64;

    const int aRowOff = (lid & 7) + ((lid >> 3) & 1) * 8;
    const uint32_t aCk = (uint32_t)(lid >> 4);
    const int bRowOff = (lid & 7) + (lid >> 4) * 8;
    const uint32_t bCk = (uint32_t)((lid >> 3) & 1);
    const uint32_t rx = (uint32_t)(lid & 7);

    const int cr = tid >> 1, ch = tid & 1;
    const uint32_t crx = (uint32_t)(cr & 7);

    for (int i = tid; i < TTILE + 2 * PAD_; i += 128) {
        int tg = t0 - PAD_ + i;
        float c0 = 0.f, c1 = 0.f;
        if (tg >= 0 && tg < T_) {
            const float* p = aw + ((size_t)b * T_ + tg) * 2;
            c0 = p[0]; c1 = p[1];
        }
        sAw[i] = c0;
        sAw[96 + i] = c1;
    }
    sPQ[tid] = g_pq[b * A_ + tid];
    sV[tid] = v[tid];
    __syncthreads();

    // -------- prologue: chunk 0 (conv) --------
    {
        unsigned char* abuf = smem + OFF_A;   // buffer 0
        float xv[8];
        #pragma unroll
        for (int j2 = 0; j2 < 4; ++j2) {
            #pragma unroll
            for (int e = 0; e < 8; ++e) {
                int j = ch * 32 + j2 * 8 + e;
                float x = 0.f;
                if (j < 62) {
                    int c = (j >= 31);
                    x = sAw[c * 96 + cr + (j - c * 31)];
                }
                xv[e] = x;
            }
            uint4 H, L;
            split2(xv[0], xv[1], H.x, L.x);
            split2(xv[2], xv[3], H.y, L.y);
            split2(xv[4], xv[5], H.z, L.z);
            split2(xv[6], xv[7], H.w, L.w);
            uint32_t c = (uint32_t)(ch * 4 + j2);
            uint32_t dst = (uint32_t)(cr << 7) + (((c ^ crx) & 7u) << 4);
            *(uint4*)(abuf + dst) = H;
            *(uint4*)(abuf + 8192 + dst) = L;
        }
        #pragma unroll
        for (int it = 0; it < 8; ++it) {
            int idx = it * 128 + tid;
            uint32_t row = (uint32_t)(idx >> 3), q = (uint32_t)(idx & 7);
            uint32_t dst = sb + OFF_B + (row << 7) + (((q ^ row) & 7u) << 4);
            cp16(dst, g_WlocH + row * 64 + q * 8);
            cp16(dst + 16384, g_WlocL + row * 64 + q * 8);
        }
        cp_commit();
        cp_wait0();
    }
    __syncthreads();

    float acc[2][8][4];
    #pragma unroll
    for (int m = 0; m < 2; ++m)
        #pragma unroll
        for (int n = 0; n < 8; ++n)
            #pragma unroll
            for (int e = 0; e < 4; ++e) acc[m][n][e] = 0.f;

    uint32_t aRowB[2], bRowB[4];
    #pragma unroll
    for (int m = 0; m < 2; ++m) aRowB[m] = (uint32_t)(tBase + m * 16 + aRowOff) << 7;
    #pragma unroll
    for (int g = 0; g < 4; ++g) bRowB[g] = (uint32_t)(aBase + g * 16 + bRowOff) << 7;

    for (int c = 0; c < NCHUNKS; ++c) {
        const uint32_t curA = sb + OFF_A + (uint32_t)(c & 1) * 16384;
        const uint32_t curB = sb + OFF_B + (uint32_t)(c & 1) * 32768;
        const bool have_next = (c + 1 < NCHUNKS);

        float4 a8[8];
        if (have_next) {
            const int kb = c * 64;   // chunk c+1 -> kbase = c*64
            const uint32_t nxtB = sb + OFF_B + (uint32_t)((c + 1) & 1) * 32768;
            const __half* WH = g_WmH + kb;
            const __half* WL = g_WmL + kb;
            #pragma unroll
            for (int it = 0; it < 8; ++it) {
                int idx = it * 128 + tid;
                uint32_t row = (uint32_t)(idx >> 3), q = (uint32_t)(idx & 7);
                uint32_t dst = nxtB + (row << 7) + (((q ^ row) & 7u) << 4);
                cp16(dst, WH + (size_t)row * E_ + q * 8);
                cp16(dst + 16384, WL + (size_t)row * E_ + q * 8);
            }
            cp_commit();
            int gt = t0 + cr;
            if (gt < T_) {
                const float* src = memory + ((size_t)b * T_ + gt) * E_ + kb + ch * 32;
                #pragma unroll
                for (int j = 0; j < 8; ++j) a8[j] = *(const float4*)(src + j * 4);
            } else {
                #pragma unroll
                for (int j = 0; j < 8; ++j) a8[j] = make_float4(0.f, 0.f, 0.f, 0.f);
            }
        }

        // ---- MMA over current chunk (pass-major: max accumulator reuse gap) ----
        #pragma unroll
        for (int ks = 0; ks < 4; ++ks) {
            uint32_t ah[2][4], al[2][4];
            #pragma unroll
            for (int m = 0; m < 2; ++m) {
                uint32_t ad = curA + aRowB[m] +
                              ((((uint32_t)(2 * ks) + aCk) ^ rx) << 4);
                LDSM4(ah[m], ad);
                LDSM4(al[m], ad + 8192);
            }
            uint32_t bh[4][4], bl[4][4];
            #pragma unroll
            for (int g = 0; g < 4; ++g) {
                uint32_t bd = curB + bRowB[g] +
                              ((((uint32_t)(2 * ks) + bCk) ^ rx) << 4);
                LDSM4(bh[g], bd);
                LDSM4(bl[g], bd + 16384);
            }
            // pass 1: hi*hi — all 16 distinct accumulators
            #pragma unroll
            for (int m = 0; m < 2; ++m)
                #pragma unroll
                for (int g = 0; g < 4; ++g) {
                    MMA16816(acc[m][2 * g],     ah[m], bh[g][0], bh[g][1]);
                    MMA16816(acc[m][2 * g + 1], ah[m], bh[g][2], bh[g][3]);
                }
            // pass 2: hi*lo
            #pragma unroll
            for (int m = 0; m < 2; ++m)
                #pragma unroll
                for (int g = 0; g < 4; ++g) {
                    MMA16816(acc[m][2 * g],     ah[m], bl[g][0], bl[g][1]);
                    MMA16816(acc[m][2 * g + 1], ah[m], bl[g][2], bl[g][3]);
                }
            // pass 3: lo*hi
            #pragma unroll
            for (int m = 0; m < 2; ++m)
                #pragma unroll
                for (int g = 0; g < 4; ++g) {
                    MMA16816(acc[m][2 * g],     al[m], bh[g][0], bh[g][1]);
                    MMA16816(acc[m][2 * g + 1], al[m], bh[g][2], bh[g][3]);
                }
        }

        if (have_next) {
            unsigned char* nb = smem + OFF_A + ((c + 1) & 1) * 16384;
            #pragma unroll
            for (int j2 = 0; j2 < 4; ++j2) {
                float4 x = a8[2 * j2], y = a8[2 * j2 + 1];
                uint4 H, L;
                split2(x.x, x.y, H.x, L.x);
                split2(x.z, x.w, H.y, L.y);
                split2(y.x, y.y, H.z, L.z);
                split2(y.z, y.w, H.w, L.w);
                uint32_t cc = (uint32_t)(ch * 4 + j2);
                uint32_t dst = (uint32_t)(cr << 7) + (((cc ^ crx) & 7u) << 4);
                *(uint4*)(nb + dst) = H;
                *(uint4*)(nb + 8192 + dst) = L;
            }
            cp_wait0();
        }
        __syncthreads();
    }

    // ---- scores: s[t] = sum_a v[a]*tanh(acc + pq[a]) ----
    {
        float s[4] = {0.f, 0.f, 0.f, 0.f};
        #pragma unroll
        for (int m = 0; m < 2; ++m) {
            #pragma unroll
            for (int n = 0; n < 8; ++n) {
                int a0 = aBase + n * 8 + (lid & 3) * 2;
                float v0 = sV[a0], v1 = sV[a0 + 1];
                float q0 = sPQ[a0], q1 = sPQ[a0 + 1];
                s[2 * m]     += v0 * tanhf(acc[m][n][0] + q0)
                              + v1 * tanhf(acc[m][n][1] + q1);
                s[2 * m + 1] += v0 * tanhf(acc[m][n][2] + q0)
                              + v1 * tanhf(acc[m][n][3] + q1);
            }
        }
        #pragma unroll
        for (int off = 1; off < 4; off <<= 1) {
            #pragma unroll
            for (int i = 0; i < 4; ++i)
                s[i] += __shfl_xor_sync(0xffffffffu, s[i], off);
        }
        if ((lid & 3) == 0) {
            int r = tBase + (lid >> 2);
            sSc[warpA * 64 + r]      = s[0];
            sSc[warpA * 64 + r + 8]  = s[1];
            sSc[warpA * 64 + r + 16] = s[2];
            sSc[warpA * 64 + r + 24] = s[3];
        }
    }
    __syncthreads();

    // ---- tile softmax partial ----
    if (tid < TTILE) {
        int gt = t0 + tid;
        float sf = sSc[tid] + sSc[64 + tid];
        bool valid = gt < T_;
        if (valid) g_scores[b * T_ + gt] = sf;
        sFin[tid] = valid ? sf : -1e30f;
    }
    __syncthreads();
    if (wid == 0) {
        float s0 = sFin[lid], s1 = sFin[lid + 32];
        float m = fmaxf(s0, s1);
        #pragma unroll
        for (int off = 16; off; off >>= 1)
            m = fmaxf(m, __shfl_xor_sync(0xffffffffu, m, off));
        float w0 = __expf(s0 - m), w1 = __expf(s1 - m);
        float l = w0 + w1;
        #pragma unroll
        for (int off = 16; off; off >>= 1)
            l += __shfl_xor_sync(0xffffffffu, l, off);
        sW[lid] = w0;
        sW[lid + 32] = w1;
        if (lid == 0) g_mtl[b * NTILES + tile] = make_float2(m, l);
    }
    __syncthreads();

    // ---- ctx partial: cpart[e] = sum_t w[t] * memory[b, t0+t, e] (L2-warm) ----
    {
        const int tmax = min(TTILE, T_ - t0);
        const float* mrow = memory + ((size_t)b * T_ + t0) * E_ + tid * 4;
        float4 acc0 = make_float4(0.f, 0.f, 0.f, 0.f);
        float4 acc1 = make_float4(0.f, 0.f, 0.f, 0.f);
        int t = 0;
        for (; t + 2 <= tmax; t += 2) {
            float w0 = sW[t], w1 = sW[t + 1];
            float4 m0 = *(const float4*)(mrow);
            float4 m1 = *(const float4*)(mrow + E_);
            mrow += 2 * E_;
            acc0.x += w0 * m0.x; acc0.y += w0 * m0.y;
            acc0.z += w0 * m0.z; acc0.w += w0 * m0.w;
            acc1.x += w1 * m1.x; acc1.y += w1 * m1.y;
            acc1.z += w1 * m1.z; acc1.w += w1 * m1.w;
        }
        if (t < tmax) {
            float w0 = sW[t];
            float4 m0 = *(const float4*)(mrow);
            acc0.x += w0 * m0.x; acc0.y += w0 * m0.y;
            acc0.z += w0 * m0.z; acc0.w += w0 * m0.w;
        }
        acc0.x += acc1.x; acc0.y += acc1.y;
        acc0.z += acc1.z; acc0.w += acc1.w;
        *((float4*)(g_cpart + ((size_t)b * NTILES + tile) * E_) + tid) = acc0;
    }
}

// ---------------------------------------------------------------------------
// combine: global softmax over tiles -> context + alignments
// grid (B_, 5): y==0 -> context, y=1..4 -> alignment quarters
// ---------------------------------------------------------------------------
__global__ void combine_kernel(float* __restrict__ ctx_out,
                               float* __restrict__ align_out) {
    __shared__ float fac[NTILES];
    __shared__ float sML[2];
    int b = blockIdx.x, part = blockIdx.y, tid = threadIdx.x;  // 512 threads
    if (tid < NTILES) {
        float2 ml = g_mtl[b * NTILES + tid];
        float M = ml.x;
        #pragma unroll
        for (int off = 16; off; off >>= 1)
            M = fmaxf(M, __shfl_xor_sync(0xffffffffu, M, off));
        float f = __expf(ml.x - M);
        float L = ml.y * f;
        #pragma unroll
        for (int off = 16; off; off >>= 1)
            L += __shfl_xor_sync(0xffffffffu, L, off);
        fac[tid] = f;
        if (tid == 0) { sML[0] = M; sML[1] = L; }
    }
    __syncthreads();
    float M = sML[0];
    float invL = 1.f / sML[1];

    if (part == 0) {
        float s = 0.f;
        #pragma unroll
        for (int i = 0; i < NTILES; ++i)
            s += g_cpart[((size_t)b * NTILES + i) * E_ + tid] * fac[i];
        ctx_out[b * E_ + tid] = s * invL;
    } else {
        int tbeg = (part - 1) * 500;
        for (int t = tbeg + tid; t < tbeg + 500; t += 512)
            align_out[b * T_ + t] = __expf(g_scores[b * T_ + t] - M) * invL;
    }
}

// ---------------------------------------------------------------------------
extern "C" void kernel_launch(void* const* d_in, const int* in_sizes, int n_in,
                              void* d_out, int out_size) {
    const float* query  = (const float*)d_in[0];  // [64,1024]
    const float* memory = (const float*)d_in[1];  // [64,2000,512]
    const float* aw     = (const float*)d_in[2];  // [64,2000,2]
    const float* Wq     = (const float*)d_in[3];  // [128,1024]
    const float* Wm     = (const float*)d_in[4];  // [128,512]
    const float* Wloc   = (const float*)d_in[5];  // [128,2,31]
    const float* v      = (const float*)d_in[6];  // [128]

    float* ctx = (float*)d_out;                   // [64,512]
    float* aligns = ctx + B_ * E_;                // [64,2000]

    cudaFuncSetAttribute(scores_fused_kernel,
                         cudaFuncAttributeMaxDynamicSharedMemorySize, SMEM_TOTAL);

    prep_kernel<<<256, 256>>>(Wm, Wloc);
    pq_kernel<<<B_, 128>>>(query, Wq);
    scores_fused_kernel<<<dim3(NTILES, B_), 128, SMEM_TOTAL>>>(memory, aw, v);
    combine_kernel<<<dim3(B_, 5), 512>>>(ctx, aligns);
}

// round 9
// speedup vs baseline: 2.9721x; 1.1541x over previous
#include <cuda_runtime.h>
#include <cuda_fp16.h>
#include <math.h>
#include <stdint.h>

#define B_   64
#define T_   2000
#define E_   512
#define D_   1024
#define A_   128
#define PAD_ 15
#define TTILE  64
#define NTILES 32          // ceil(2000/64)
#define NCHUNKS 9          // chunk 0 = conv (im2col), 1..8 = memory K

// ---- device scratch (allocation-free rule) ----
__device__ __align__(16) float  g_pq[B_ * A_];
__device__ __align__(16) float  g_scores[B_ * T_];
__device__ __align__(16) float  g_cpart[B_ * NTILES * E_];
__device__ __align__(16) float2 g_mtl[B_ * NTILES];
__device__ __align__(16) __half g_WmH[A_ * E_], g_WmL[A_ * E_];
__device__ __align__(16) __half g_WlocH[A_ * 64], g_WlocL[A_ * 64];

// ---- smem layout (bytes) ----
#define S_AW   0            // 2 x 96 floats = 768
#define S_PQ   768          // 128 floats
#define S_V    1280         // 128 floats
#define S_SC   1792         // 2 x 64 floats = 512
#define S_BUF  2304
#define OFF_A  S_BUF        // 2 bufs x 16384 (AH 8192 + AL 8192), 64 rows x 128B
#define OFF_B  (S_BUF + 32768)  // SINGLE buf 32768 (BH 16384 + BL 16384)
#define S_FIN  (OFF_B + 32768)  // 64 floats
#define S_W    (S_FIN + 256)    // 64 floats
#define SMEM_TOTAL (S_W + 256)  // 68352 -> 3 CTAs/SM

// ---------------- PTX helpers ----------------
__device__ __forceinline__ uint32_t smem_u32(const void* p) {
    uint32_t a;
    asm("{ .reg .u64 t; cvta.to.shared.u64 t, %1; cvt.u32.u64 %0, t; }"
        : "=r"(a) : "l"(p));
    return a;
}
__device__ __forceinline__ void cp16(uint32_t dst, const void* src) {
    asm volatile("cp.async.cg.shared.global [%0], [%1], 16;"
                 :: "r"(dst), "l"(src) : "memory");
}
__device__ __forceinline__ void cp_commit() {
    asm volatile("cp.async.commit_group;" ::: "memory");
}
__device__ __forceinline__ void cp_wait0() {
    asm volatile("cp.async.wait_group 0;" ::: "memory");
}
#define LDSM4(R, addr)                                                        \
    asm volatile("ldmatrix.sync.aligned.m8n8.x4.shared.b16 {%0,%1,%2,%3}, [%4];" \
                 : "=r"((R)[0]), "=r"((R)[1]), "=r"((R)[2]), "=r"((R)[3])     \
                 : "r"(addr))
#define MMA16816(acc, Af, b0, b1)                                             \
    asm volatile("mma.sync.aligned.m16n8k16.row.col.f32.f16.f16.f32 "         \
                 "{%0,%1,%2,%3},{%4,%5,%6,%7},{%8,%9},{%0,%1,%2,%3};"         \
                 : "+f"((acc)[0]), "+f"((acc)[1]), "+f"((acc)[2]), "+f"((acc)[3]) \
                 : "r"((Af)[0]), "r"((Af)[1]), "r"((Af)[2]), "r"((Af)[3]),    \
                   "r"(b0), "r"(b1))

__device__ __forceinline__ void split2(float x, float y,
                                       uint32_t& hi, uint32_t& lo) {
    __half hx = __float2half_rn(x), hy = __float2half_rn(y);
    __half lx = __float2half_rn(x - __half2float(hx));
    __half ly = __float2half_rn(y - __half2float(hy));
    __half2 H = __halves2half2(hx, hy), L = __halves2half2(lx, ly);
    hi = *(uint32_t*)&H;
    lo = *(uint32_t*)&L;
}

// ---------------------------------------------------------------------------
// merged prep (Wm/Wloc fp16 split) + pq GEMV
// grid 320 x 256 threads: blocks 0..255 -> prep, 256..319 -> pq
// ---------------------------------------------------------------------------
__global__ void prep_pq_kernel(const float* __restrict__ Wm,
                               const float* __restrict__ Wloc,
                               const float* __restrict__ query,
                               const float* __restrict__ Wq) {
    if (blockIdx.x < 256) {
        int idx = blockIdx.x * 256 + threadIdx.x;    // 65536
        float x = Wm[idx];
        __half h = __float2half_rn(x);
        __half l = __float2half_rn(x - __half2float(h));
        g_WmH[idx] = h;
        g_WmL[idx] = l;
        if (idx < A_ * 64) {
            int j = idx & 63;
            float w = (j < 62) ? Wloc[(idx >> 6) * 62 + j] : 0.f;
            __half wh = __float2half_rn(w);
            __half wl = __float2half_rn(w - __half2float(wh));
            g_WlocH[idx] = wh;
            g_WlocL[idx] = wl;
        }
    } else {
        int b = blockIdx.x - 256;
        int warp = threadIdx.x >> 5, lane = threadIdx.x & 31;
        const float* q = query + (size_t)b * D_;
        for (int a = warp; a < A_; a += 8) {
            const float* w = Wq + (size_t)a * D_;
            float s = 0.f;
            for (int k = lane; k < D_; k += 32) s += q[k] * w[k];
            #pragma unroll
            for (int off = 16; off; off >>= 1)
                s += __shfl_xor_sync(0xffffffffu, s, off);
            if (lane == 0) g_pq[b * A_ + a] = s;
        }
    }
}

// no-op kernels: shift scores_fused to launch index 3 for ncu capture
__global__ void dummy_kernel_a() {}
__global__ void dummy_kernel_b() {}

// ---------------------------------------------------------------------------
// fused: scores (fp16-split HMMA) + tile softmax partial + ctx partial
// 64t x 128a tile, 128 threads, 3 CTAs/SM (B single-buffered).
// ---------------------------------------------------------------------------
__global__ void __launch_bounds__(128, 3)
scores_fused_kernel(const float* __restrict__ memory,
                    const float* __restrict__ aw,
                    const float* __restrict__ v) {
    extern __shared__ unsigned char smem[];
    const uint32_t sb = smem_u32(smem);
    const int tid = threadIdx.x;
    const int wid = tid >> 5, lid = tid & 31;
    const int b = blockIdx.y;
    const int tile = blockIdx.x;
    const int t0 = tile * TTILE;

    float* sAw  = (float*)(smem + S_AW);     // [2][96]
    float* sPQ  = (float*)(smem + S_PQ);
    float* sV   = (float*)(smem + S_V);
    float* sSc  = (float*)(smem + S_SC);     // [2][64]
    float* sFin = (float*)(smem + S_FIN);    // [64]
    float* sW   = (float*)(smem + S_W);      // [64]

    const int warpT = wid >> 1, warpA = wid & 1;
    const int tBase = warpT * 32;
    const int aBase = warpA * 64;

    const int aRowOff = (lid & 7) + ((lid >> 3) & 1) * 8;
    const uint32_t aCk = (uint32_t)(lid >> 4);
    const int bRowOff = (lid & 7) + (lid >> 4) * 8;
    const uint32_t bCk = (uint32_t)((lid >> 3) & 1);
    const uint32_t rx = (uint32_t)(lid & 7);

    const int cr = tid >> 1, ch = tid & 1;
    const uint32_t crx = (uint32_t)(cr & 7);

    for (int i = tid; i < TTILE + 2 * PAD_; i += 128) {
        int tg = t0 - PAD_ + i;
        float c0 = 0.f, c1 = 0.f;
        if (tg >= 0 && tg < T_) {
            const float* p = aw + ((size_t)b * T_ + tg) * 2;
            c0 = p[0]; c1 = p[1];
        }
        sAw[i] = c0;
        sAw[96 + i] = c1;
    }
    sPQ[tid] = g_pq[b * A_ + tid];
    sV[tid] = v[tid];
    __syncthreads();

    // -------- prologue: chunk 0 (conv) --------
    {
        unsigned char* abuf = smem + OFF_A;   // A buffer 0
        float xv[8];
        #pragma unroll
        for (int j2 = 0; j2 < 4; ++j2) {
            #pragma unroll
            for (int e = 0; e < 8; ++e) {
                int j = ch * 32 + j2 * 8 + e;
                float x = 0.f;
                if (j < 62) {
                    int c = (j >= 31);
                    x = sAw[c * 96 + cr + (j - c * 31)];
                }
                xv[e] = x;
            }
            uint4 H, L;
            split2(xv[0], xv[1], H.x, L.x);
            split2(xv[2], xv[3], H.y, L.y);
            split2(xv[4], xv[5], H.z, L.z);
            split2(xv[6], xv[7], H.w, L.w);
            uint32_t c = (uint32_t)(ch * 4 + j2);
            uint32_t dst = (uint32_t)(cr << 7) + (((c ^ crx) & 7u) << 4);
            *(uint4*)(abuf + dst) = H;
            *(uint4*)(abuf + 8192 + dst) = L;
        }
        #pragma unroll
        for (int it = 0; it < 8; ++it) {
            int idx = it * 128 + tid;
            uint32_t row = (uint32_t)(idx >> 3), q = (uint32_t)(idx & 7);
            uint32_t dst = sb + OFF_B + (row << 7) + (((q ^ row) & 7u) << 4);
            cp16(dst, g_WlocH + row * 64 + q * 8);
            cp16(dst + 16384, g_WlocL + row * 64 + q * 8);
        }
        cp_commit();
        cp_wait0();
    }
    __syncthreads();

    float acc[2][8][4];
    #pragma unroll
    for (int m = 0; m < 2; ++m)
        #pragma unroll
        for (int n = 0; n < 8; ++n)
            #pragma unroll
            for (int e = 0; e < 4; ++e) acc[m][n][e] = 0.f;

    uint32_t aRowB[2], bRowB[4];
    #pragma unroll
    for (int m = 0; m < 2; ++m) aRowB[m] = (uint32_t)(tBase + m * 16 + aRowOff) << 7;
    #pragma unroll
    for (int g = 0; g < 4; ++g) bRowB[g] = (uint32_t)(aBase + g * 16 + bRowOff) << 7;

    const uint32_t curB = sb + OFF_B;   // single B buffer

    for (int c = 0; c < NCHUNKS; ++c) {
        const uint32_t curA = sb + OFF_A + (uint32_t)(c & 1) * 16384;
        const bool have_next = (c + 1 < NCHUNKS);

        float4 a8[8];
        if (have_next) {
            const int kb = c * 64;   // chunk c+1 -> kbase = c*64
            int gt = t0 + cr;
            if (gt < T_) {
                const float* src = memory + ((size_t)b * T_ + gt) * E_ + kb + ch * 32;
                #pragma unroll
                for (int j = 0; j < 8; ++j) a8[j] = *(const float4*)(src + j * 4);
            } else {
                #pragma unroll
                for (int j = 0; j < 8; ++j) a8[j] = make_float4(0.f, 0.f, 0.f, 0.f);
            }
        }

        // ---- MMA over current chunk (pass-major) ----
        #pragma unroll
        for (int ks = 0; ks < 4; ++ks) {
            uint32_t ah[2][4], al[2][4];
            #pragma unroll
            for (int m = 0; m < 2; ++m) {
                uint32_t ad = curA + aRowB[m] +
                              ((((uint32_t)(2 * ks) + aCk) ^ rx) << 4);
                LDSM4(ah[m], ad);
                LDSM4(al[m], ad + 8192);
            }
            uint32_t bh[4][4], bl[4][4];
            #pragma unroll
            for (int g = 0; g < 4; ++g) {
                uint32_t bd = curB + bRowB[g] +
                              ((((uint32_t)(2 * ks) + bCk) ^ rx) << 4);
                LDSM4(bh[g], bd);
                LDSM4(bl[g], bd + 16384);
            }
            #pragma unroll
            for (int m = 0; m < 2; ++m)
                #pragma unroll
                for (int g = 0; g < 4; ++g) {
                    MMA16816(acc[m][2 * g],     ah[m], bh[g][0], bh[g][1]);
                    MMA16816(acc[m][2 * g + 1], ah[m], bh[g][2], bh[g][3]);
                }
            #pragma unroll
            for (int m = 0; m < 2; ++m)
                #pragma unroll
                for (int g = 0; g < 4; ++g) {
                    MMA16816(acc[m][2 * g],     ah[m], bl[g][0], bl[g][1]);
                    MMA16816(acc[m][2 * g + 1], ah[m], bl[g][2], bl[g][3]);
                }
            #pragma unroll
            for (int m = 0; m < 2; ++m)
                #pragma unroll
                for (int g = 0; g < 4; ++g) {
                    MMA16816(acc[m][2 * g],     al[m], bh[g][0], bh[g][1]);
                    MMA16816(acc[m][2 * g + 1], al[m], bh[g][2], bh[g][3]);
                }
        }

        __syncthreads();   // B consumed by all warps

        if (have_next) {
            // refill single B buffer for chunk c+1
            const int kb = c * 64;
            const __half* WH = g_WmH + kb;
            const __half* WL = g_WmL + kb;
            #pragma unroll
            for (int it = 0; it < 8; ++it) {
                int idx = it * 128 + tid;
                uint32_t row = (uint32_t)(idx >> 3), q = (uint32_t)(idx & 7);
                uint32_t dst = sb + OFF_B + (row << 7) + (((q ^ row) & 7u) << 4);
                cp16(dst, WH + (size_t)row * E_ + q * 8);
                cp16(dst + 16384, WL + (size_t)row * E_ + q * 8);
            }
            cp_commit();

            // convert + store A(c+1) into other A buffer (overlaps cp.async)
            unsigned char* nb = smem + OFF_A + ((c + 1) & 1) * 16384;
            #pragma unroll
            for (int j2 = 0; j2 < 4; ++j2) {
                float4 x = a8[2 * j2], y = a8[2 * j2 + 1];
                uint4 H, L;
                split2(x.x, x.y, H.x, L.x);
                split2(x.z, x.w, H.y, L.y);
                split2(y.x, y.y, H.z, L.z);
                split2(y.z, y.w, H.w, L.w);
                uint32_t cc = (uint32_t)(ch * 4 + j2);
                uint32_t dst = (uint32_t)(cr << 7) + (((cc ^ crx) & 7u) << 4);
                *(uint4*)(nb + dst) = H;
                *(uint4*)(nb + 8192 + dst) = L;
            }
            cp_wait0();
        }
        __syncthreads();
    }

    // ---- scores: s[t] = sum_a v[a]*tanh(acc + pq[a]) ----
    {
        float s[4] = {0.f, 0.f, 0.f, 0.f};
        #pragma unroll
        for (int m = 0; m < 2; ++m) {
            #pragma unroll
            for (int n = 0; n < 8; ++n) {
                int a0 = aBase + n * 8 + (lid & 3) * 2;
                float v0 = sV[a0], v1 = sV[a0 + 1];
                float q0 = sPQ[a0], q1 = sPQ[a0 + 1];
                s[2 * m]     += v0 * tanhf(acc[m][n][0] + q0)
                              + v1 * tanhf(acc[m][n][1] + q1);
                s[2 * m + 1] += v0 * tanhf(acc[m][n][2] + q0)
                              + v1 * tanhf(acc[m][n][3] + q1);
            }
        }
        #pragma unroll
        for (int off = 1; off < 4; off <<= 1) {
            #pragma unroll
            for (int i = 0; i < 4; ++i)
                s[i] += __shfl_xor_sync(0xffffffffu, s[i], off);
        }
        if ((lid & 3) == 0) {
            int r = tBase + (lid >> 2);
            sSc[warpA * 64 + r]      = s[0];
            sSc[warpA * 64 + r + 8]  = s[1];
            sSc[warpA * 64 + r + 16] = s[2];
            sSc[warpA * 64 + r + 24] = s[3];
        }
    }
    __syncthreads();

    // ---- tile softmax partial ----
    if (tid < TTILE) {
        int gt = t0 + tid;
        float sf = sSc[tid] + sSc[64 + tid];
        bool valid = gt < T_;
        if (valid) g_scores[b * T_ + gt] = sf;
        sFin[tid] = valid ? sf : -1e30f;
    }
    __syncthreads();
    if (wid == 0) {
        float s0 = sFin[lid], s1 = sFin[lid + 32];
        float m = fmaxf(s0, s1);
        #pragma unroll
        for (int off = 16; off; off >>= 1)
            m = fmaxf(m, __shfl_xor_sync(0xffffffffu, m, off));
        float w0 = __expf(s0 - m), w1 = __expf(s1 - m);
        float l = w0 + w1;
        #pragma unroll
        for (int off = 16; off; off >>= 1)
            l += __shfl_xor_sync(0xffffffffu, l, off);
        sW[lid] = w0;
        sW[lid + 32] = w1;
        if (lid == 0) g_mtl[b * NTILES + tile] = make_float2(m, l);
    }
    __syncthreads();

    // ---- ctx partial: cpart[e] = sum_t w[t] * memory[b, t0+t, e] (L2-warm) ----
    {
        const int tmax = min(TTILE, T_ - t0);
        const float* mrow = memory + ((size_t)b * T_ + t0) * E_ + tid * 4;
        float4 acc0 = make_float4(0.f, 0.f, 0.f, 0.f);
        float4 acc1 = make_float4(0.f, 0.f, 0.f, 0.f);
        int t = 0;
        for (; t + 2 <= tmax; t += 2) {
            float w0 = sW[t], w1 = sW[t + 1];
            float4 m0 = *(const float4*)(mrow);
            float4 m1 = *(const float4*)(mrow + E_);
            mrow += 2 * E_;
            acc0.x += w0 * m0.x; acc0.y += w0 * m0.y;
            acc0.z += w0 * m0.z; acc0.w += w0 * m0.w;
            acc1.x += w1 * m1.x; acc1.y += w1 * m1.y;
            acc1.z += w1 * m1.z; acc1.w += w1 * m1.w;
        }
        if (t < tmax) {
            float w0 = sW[t];
            float4 m0 = *(const float4*)(mrow);
            acc0.x += w0 * m0.x; acc0.y += w0 * m0.y;
            acc0.z += w0 * m0.z; acc0.w += w0 * m0.w;
        }
        acc0.x += acc1.x; acc0.y += acc1.y;
        acc0.z += acc1.z; acc0.w += acc1.w;
        *((float4*)(g_cpart + ((size_t)b * NTILES + tile) * E_) + tid) = acc0;
    }
}

// ---------------------------------------------------------------------------
// combine: global softmax over tiles -> context + alignments
// grid (B_, 5): y==0 -> context, y=1..4 -> alignment quarters
// ---------------------------------------------------------------------------
__global__ void combine_kernel(float* __restrict__ ctx_out,
                               float* __restrict__ align_out) {
    __shared__ float fac[NTILES];
    __shared__ float sML[2];
    int b = blockIdx.x, part = blockIdx.y, tid = threadIdx.x;  // 512 threads
    if (tid < NTILES) {
        float2 ml = g_mtl[b * NTILES + tid];
        float M = ml.x;
        #pragma unroll
        for (int off = 16; off; off >>= 1)
            M = fmaxf(M, __shfl_xor_sync(0xffffffffu, M, off));
        float f = __expf(ml.x - M);
        float L = ml.y * f;
        #pragma unroll
        for (int off = 16; off; off >>= 1)
            L += __shfl_xor_sync(0xffffffffu, L, off);
        fac[tid] = f;
        if (tid == 0) { sML[0] = M; sML[1] = L; }
    }
    __syncthreads();
    float M = sML[0];
    float invL = 1.f / sML[1];

    if (part == 0) {
        float s = 0.f;
        #pragma unroll
        for (int i = 0; i < NTILES; ++i)
            s += g_cpart[((size_t)b * NTILES + i) * E_ + tid] * fac[i];
        ctx_out[b * E_ + tid] = s * invL;
    } else {
        int tbeg = (part - 1) * 500;
        for (int t = tbeg + tid; t < tbeg + 500; t += 512)
            align_out[b * T_ + t] = __expf(g_scores[b * T_ + t] - M) * invL;
    }
}

// ---------------------------------------------------------------------------
extern "C" void kernel_launch(void* const* d_in, const int* in_sizes, int n_in,
                              void* d_out, int out_size) {
    const float* query  = (const float*)d_in[0];  // [64,1024]
    const float* memory = (const float*)d_in[1];  // [64,2000,512]
    const float* aw     = (const float*)d_in[2];  // [64,2000,2]
    const float* Wq     = (const float*)d_in[3];  // [128,1024]
    const float* Wm     = (const float*)d_in[4];  // [128,512]
    const float* Wloc   = (const float*)d_in[5];  // [128,2,31]
    const float* v      = (const float*)d_in[6];  // [128]

    float* ctx = (float*)d_out;                   // [64,512]
    float* aligns = ctx + B_ * E_;                // [64,2000]

    cudaFuncSetAttribute(scores_fused_kernel,
                         cudaFuncAttributeMaxDynamicSharedMemorySize, SMEM_TOTAL);

    prep_pq_kernel<<<320, 256>>>(Wm, Wloc, query, Wq);   // launch 0
    dummy_kernel_a<<<1, 32>>>();                         // launch 1
    dummy_kernel_b<<<1, 32>>>();                         // launch 2
    scores_fused_kernel<<<dim3(NTILES, B_), 128, SMEM_TOTAL>>>(memory, aw, v); // 3
    combine_kernel<<<dim3(B_, 5), 512>>>(ctx, aligns);   // launch 4
}

// round 10
// speedup vs baseline: 3.3389x; 1.1234x over previous
#include <cuda_runtime.h>
#include <cuda_fp16.h>
#include <math.h>
#include <stdint.h>

#define B_   64
#define T_   2000
#define E_   512
#define D_   1024
#define A_   128
#define PAD_ 15
#define TTILE  64
#define NTILES 32          // ceil(2000/64)
#define NCHUNKS 9          // chunk 0 = conv (im2col), 1..8 = memory K

// ---- device scratch (allocation-free rule) ----
__device__ __align__(16) float  g_pq[B_ * A_];
__device__ __align__(16) float  g_scores[B_ * T_];
__device__ __align__(16) float  g_cpart[B_ * NTILES * E_];
__device__ __align__(16) float2 g_mtl[B_ * NTILES];
__device__ __align__(16) __half g_WmH[A_ * E_], g_WmL[A_ * E_];
__device__ __align__(16) __half g_WlocH[A_ * 64], g_WlocL[A_ * 64];

// ---- smem layout (bytes) ----
#define S_AW   0            // 2 x 96 floats = 768
#define S_PQ   768          // 128 floats
#define S_V    1280         // 128 floats
#define S_SC   1792         // 2 x 64 floats = 512
#define S_FIN  2304         // 64 floats
#define S_W    2560         // 64 floats
#define OFF_B  2816         // 2 bufs x 32768 (BH 16384 | BL 16384)
#define SMEM_TOTAL (OFF_B + 65536)   // 68352 -> 3 CTAs/SM

// ---------------- PTX helpers ----------------
__device__ __forceinline__ uint32_t smem_u32(const void* p) {
    uint32_t a;
    asm("{ .reg .u64 t; cvta.to.shared.u64 t, %1; cvt.u32.u64 %0, t; }"
        : "=r"(a) : "l"(p));
    return a;
}
__device__ __forceinline__ void cp16(uint32_t dst, const void* src) {
    asm volatile("cp.async.cg.shared.global [%0], [%1], 16;"
                 :: "r"(dst), "l"(src) : "memory");
}
__device__ __forceinline__ void cp_commit() {
    asm volatile("cp.async.commit_group;" ::: "memory");
}
__device__ __forceinline__ void cp_wait0() {
    asm volatile("cp.async.wait_group 0;" ::: "memory");
}
#define LDSM4(R, addr)                                                        \
    asm volatile("ldmatrix.sync.aligned.m8n8.x4.shared.b16 {%0,%1,%2,%3}, [%4];" \
                 : "=r"((R)[0]), "=r"((R)[1]), "=r"((R)[2]), "=r"((R)[3])     \
                 : "r"(addr))
#define MMA16816(acc, Af, b0, b1)                                             \
    asm volatile("mma.sync.aligned.m16n8k16.row.col.f32.f16.f16.f32 "         \
                 "{%0,%1,%2,%3},{%4,%5,%6,%7},{%8,%9},{%0,%1,%2,%3};"         \
                 : "+f"((acc)[0]), "+f"((acc)[1]), "+f"((acc)[2]), "+f"((acc)[3]) \
                 : "r"((Af)[0]), "r"((Af)[1]), "r"((Af)[2]), "r"((Af)[3]),    \
                   "r"(b0), "r"(b1))

__device__ __forceinline__ void split2(float x, float y,
                                       uint32_t& hi, uint32_t& lo) {
    __half hx = __float2half_rn(x), hy = __float2half_rn(y);
    __half lx = __float2half_rn(x - __half2float(hx));
    __half ly = __float2half_rn(y - __half2float(hy));
    __half2 H = __halves2half2(hx, hy), L = __halves2half2(lx, ly);
    hi = *(uint32_t*)&H;
    lo = *(uint32_t*)&L;
}

// ---------------------------------------------------------------------------
// merged prep (Wm/Wloc fp16 split) + pq GEMV
// ---------------------------------------------------------------------------
__global__ void prep_pq_kernel(const float* __restrict__ Wm,
                               const float* __restrict__ Wloc,
                               const float* __restrict__ query,
                               const float* __restrict__ Wq) {
    if (blockIdx.x < 256) {
        int idx = blockIdx.x * 256 + threadIdx.x;    // 65536
        float x = Wm[idx];
        __half h = __float2half_rn(x);
        __half l = __float2half_rn(x - __half2float(h));
        g_WmH[idx] = h;
        g_WmL[idx] = l;
        if (idx < A_ * 64) {
            int j = idx & 63;
            float w = (j < 62) ? Wloc[(idx >> 6) * 62 + j] : 0.f;
            __half wh = __float2half_rn(w);
            __half wl = __float2half_rn(w - __half2float(wh));
            g_WlocH[idx] = wh;
            g_WlocL[idx] = wl;
        }
    } else {
        int b = blockIdx.x - 256;
        int warp = threadIdx.x >> 5, lane = threadIdx.x & 31;
        const float* q = query + (size_t)b * D_;
        for (int a = warp; a < A_; a += 8) {
            const float* w = Wq + (size_t)a * D_;
            float s = 0.f;
            for (int k = lane; k < D_; k += 32) s += q[k] * w[k];
            #pragma unroll
            for (int off = 16; off; off >>= 1)
                s += __shfl_xor_sync(0xffffffffu, s, off);
            if (lane == 0) g_pq[b * A_ + a] = s;
        }
    }
}

// no-op kernels: keep scores_fused at launch index 3 for ncu capture
__global__ void dummy_kernel_a() {}
__global__ void dummy_kernel_b() {}

// ---------------------------------------------------------------------------
// one k-step: LDSM B frags + 48 MMAs (hh, hl, lh)
// ---------------------------------------------------------------------------
__device__ __forceinline__ void mma_step(
    float (&acc)[2][8][4], const uint32_t* ah, const uint32_t* al,
    uint32_t curB, int ks, const uint32_t (&bRowB)[4],
    uint32_t bCk, uint32_t rx) {
    uint32_t bh[4][4], bl[4][4];
    #pragma unroll
    for (int g4 = 0; g4 < 4; ++g4) {
        uint32_t bd = curB + bRowB[g4] +
                      ((((uint32_t)(2 * ks) + bCk) ^ rx) << 4);
        LDSM4(bh[g4], bd);
        LDSM4(bl[g4], bd + 16384);
    }
    #pragma unroll
    for (int m = 0; m < 2; ++m)
        #pragma unroll
        for (int g4 = 0; g4 < 4; ++g4) {
            MMA16816(acc[m][2 * g4],     ah + 4 * m, bh[g4][0], bh[g4][1]);
            MMA16816(acc[m][2 * g4 + 1], ah + 4 * m, bh[g4][2], bh[g4][3]);
        }
    #pragma unroll
    for (int m = 0; m < 2; ++m)
        #pragma unroll
        for (int g4 = 0; g4 < 4; ++g4) {
            MMA16816(acc[m][2 * g4],     ah + 4 * m, bl[g4][0], bl[g4][1]);
            MMA16816(acc[m][2 * g4 + 1], ah + 4 * m, bl[g4][2], bl[g4][3]);
        }
    #pragma unroll
    for (int m = 0; m < 2; ++m)
        #pragma unroll
        for (int g4 = 0; g4 < 4; ++g4) {
            MMA16816(acc[m][2 * g4],     al + 4 * m, bh[g4][0], bh[g4][1]);
            MMA16816(acc[m][2 * g4 + 1], al + 4 * m, bh[g4][2], bh[g4][3]);
        }
}

// ---------------------------------------------------------------------------
// fused: scores (fp16-split HMMA, A direct-from-global fragments) +
//        tile softmax partial + ctx partial. 64t x 128a, 128 thr, 3 CTAs/SM.
// ---------------------------------------------------------------------------
__global__ void __launch_bounds__(128, 3)
scores_fused_kernel(const float* __restrict__ memory,
                    const float* __restrict__ aw,
                    const float* __restrict__ v) {
    extern __shared__ unsigned char smem[];
    const uint32_t sb = smem_u32(smem);
    const int tid = threadIdx.x;
    const int wid = tid >> 5, lid = tid & 31;
    const int b = blockIdx.y;
    const int tile = blockIdx.x;
    const int t0 = tile * TTILE;

    float* sAw  = (float*)(smem + S_AW);     // [2][96]
    float* sPQ  = (float*)(smem + S_PQ);
    float* sV   = (float*)(smem + S_V);
    float* sSc  = (float*)(smem + S_SC);     // [2][64]
    float* sFin = (float*)(smem + S_FIN);    // [64]
    float* sW   = (float*)(smem + S_W);      // [64]

    const int warpT = wid >> 1, warpA = wid & 1;
    const int tBase = warpT * 32;
    const int aBase = warpA * 64;

    // B ldmatrix lane offsets (unchanged)
    const int bRowOff = (lid & 7) + (lid >> 4) * 8;
    const uint32_t bCk = (uint32_t)((lid >> 3) & 1);
    const uint32_t rx = (uint32_t)(lid & 7);

    // A fragment lane coords (mma m16n8k16 A layout)
    const int g = lid >> 2;          // row within 8
    const int cq = (lid & 3) * 2;    // col pair base

    for (int i = tid; i < TTILE + 2 * PAD_; i += 128) {
        int tg = t0 - PAD_ + i;
        float c0 = 0.f, c1 = 0.f;
        if (tg >= 0 && tg < T_) {
            const float* p = aw + ((size_t)b * T_ + tg) * 2;
            c0 = p[0]; c1 = p[1];
        }
        sAw[i] = c0;
        sAw[96 + i] = c1;
    }
    sPQ[tid] = g_pq[b * A_ + tid];
    sV[tid] = v[tid];

    // prologue: Wloc (conv B) into buf0
    #pragma unroll
    for (int it = 0; it < 8; ++it) {
        int idx = it * 128 + tid;
        uint32_t row = (uint32_t)(idx >> 3), q = (uint32_t)(idx & 7);
        uint32_t dst = sb + OFF_B + (row << 7) + (((q ^ row) & 7u) << 4);
        cp16(dst, g_WlocH + row * 64 + q * 8);
        cp16(dst + 16384, g_WlocL + row * 64 + q * 8);
    }
    cp_commit();
    cp_wait0();
    __syncthreads();

    // A row pointers + validity (rows fixed per thread)
    const float* pb = memory +
        ((size_t)b * T_ + (size_t)(t0 + tBase + g)) * E_ + cq;
    bool vr[4];
    #pragma unroll
    for (int j = 0; j < 4; ++j) vr[j] = (t0 + tBase + g + 8 * j) < T_;

    // raw A for memory k-step 0 (cols 0..15) — preload early
    float2 f[8];
    #pragma unroll
    for (int i = 0; i < 8; ++i) {
        int ri = ((i >> 2) << 1) | (i & 1);
        const float* p = pb + (size_t)(8 * ri) * E_ + (((i >> 1) & 1) << 3);
        f[i] = vr[ri] ? *(const float2*)p : make_float2(0.f, 0.f);
    }

    float acc[2][8][4];
    #pragma unroll
    for (int m = 0; m < 2; ++m)
        #pragma unroll
        for (int n = 0; n < 8; ++n)
            #pragma unroll
            for (int e = 0; e < 4; ++e) acc[m][n][e] = 0.f;

    uint32_t bRowB[4];
    #pragma unroll
    for (int g4 = 0; g4 < 4; ++g4)
        bRowB[g4] = (uint32_t)(aBase + g4 * 16 + bRowOff) << 7;

    // ---- conv chunk (c=0): A frags from sAw, B in buf0 ----
    {
        // issue B for chunk 1 (memory cols 0..63) into buf1
        #pragma unroll
        for (int it = 0; it < 8; ++it) {
            int idx = it * 128 + tid;
            uint32_t row = (uint32_t)(idx >> 3), q = (uint32_t)(idx & 7);
            uint32_t dst = sb + OFF_B + 32768 +
                           (row << 7) + (((q ^ row) & 7u) << 4);
            cp16(dst, g_WmH + (size_t)row * E_ + q * 8);
            cp16(dst + 16384, g_WmL + (size_t)row * E_ + q * 8);
        }
        cp_commit();
        const uint32_t curB = sb + OFF_B;
        #pragma unroll
        for (int ks = 0; ks < 4; ++ks) {
            uint32_t ah[8], al[8];
            #pragma unroll
            for (int i = 0; i < 8; ++i) {
                int r = tBase + ((i >> 2) << 4) + g + ((i & 1) << 3);
                int j0 = (ks << 4) + cq + (((i >> 1) & 1) << 3);
                float x0 = 0.f, x1 = 0.f;
                if (j0 < 62) {
                    int cj = j0 >= 31;
                    x0 = sAw[cj * 96 + r + (j0 - cj * 31)];
                }
                if (j0 + 1 < 62) {
                    int cj = (j0 + 1) >= 31;
                    x1 = sAw[cj * 96 + r + (j0 + 1 - cj * 31)];
                }
                split2(x0, x1, ah[i], al[i]);
            }
            mma_step(acc, ah, al, curB, ks, bRowB, bCk, rx);
        }
        cp_wait0();
        __syncthreads();
    }

    // ---- memory chunks c = 1..8 ----
    for (int c = 1; c <= 8; ++c) {
        const uint32_t curB = sb + OFF_B + (uint32_t)(c & 1) * 32768;
        if (c < 8) {
            const __half* WH = g_WmH + c * 64;
            const __half* WL = g_WmL + c * 64;
            uint32_t nxtB = sb + OFF_B + (uint32_t)((c + 1) & 1) * 32768;
            #pragma unroll
            for (int it = 0; it < 8; ++it) {
                int idx = it * 128 + tid;
                uint32_t row = (uint32_t)(idx >> 3), q = (uint32_t)(idx & 7);
                uint32_t dst = nxtB + (row << 7) + (((q ^ row) & 7u) << 4);
                cp16(dst, WH + (size_t)row * E_ + q * 8);
                cp16(dst + 16384, WL + (size_t)row * E_ + q * 8);
            }
            cp_commit();
        }
        #pragma unroll
        for (int ks = 0; ks < 4; ++ks) {
            int s = (c - 1) * 4 + ks;            // current memory k-step
            // prefetch raw A for step s+1
            float2 fn[8];
            bool more = s < 31;
            const float* pc = pb + (size_t)(s + 1) * 16;
            #pragma unroll
            for (int i = 0; i < 8; ++i) {
                int ri = ((i >> 2) << 1) | (i & 1);
                const float* p = pc + (size_t)(8 * ri) * E_ +
                                 (((i >> 1) & 1) << 3);
                fn[i] = (more && vr[ri]) ? *(const float2*)p
                                         : make_float2(0.f, 0.f);
            }
            // convert current raw -> frags
            uint32_t ah[8], al[8];
            #pragma unroll
            for (int i = 0; i < 8; ++i)
                split2(f[i].x, f[i].y, ah[i], al[i]);
            mma_step(acc, ah, al, curB, ks, bRowB, bCk, rx);
            #pragma unroll
            for (int i = 0; i < 8; ++i) f[i] = fn[i];
        }
        if (c < 8) cp_wait0();
        __syncthreads();
    }

    // ---- scores: s[t] = sum_a v[a]*tanh(acc + pq[a]) ----
    {
        float s[4] = {0.f, 0.f, 0.f, 0.f};
        #pragma unroll
        for (int m = 0; m < 2; ++m) {
            #pragma unroll
            for (int n = 0; n < 8; ++n) {
                int a0 = aBase + n * 8 + (lid & 3) * 2;
                float v0 = sV[a0], v1 = sV[a0 + 1];
                float q0 = sPQ[a0], q1 = sPQ[a0 + 1];
                s[2 * m]     += v0 * tanhf(acc[m][n][0] + q0)
                              + v1 * tanhf(acc[m][n][1] + q1);
                s[2 * m + 1] += v0 * tanhf(acc[m][n][2] + q0)
                              + v1 * tanhf(acc[m][n][3] + q1);
            }
        }
        #pragma unroll
        for (int off = 1; off < 4; off <<= 1) {
            #pragma unroll
            for (int i = 0; i < 4; ++i)
                s[i] += __shfl_xor_sync(0xffffffffu, s[i], off);
        }
        if ((lid & 3) == 0) {
            int r = tBase + (lid >> 2);
            sSc[warpA * 64 + r]      = s[0];
            sSc[warpA * 64 + r + 8]  = s[1];
            sSc[warpA * 64 + r + 16] = s[2];
            sSc[warpA * 64 + r + 24] = s[3];
        }
    }
    __syncthreads();

    // ---- tile softmax partial ----
    if (tid < TTILE) {
        int gt = t0 + tid;
        float sf = sSc[tid] + sSc[64 + tid];
        bool valid = gt < T_;
        if (valid) g_scores[b * T_ + gt] = sf;
        sFin[tid] = valid ? sf : -1e30f;
    }
    __syncthreads();
    if (wid == 0) {
        float s0 = sFin[lid], s1 = sFin[lid + 32];
        float m = fmaxf(s0, s1);
        #pragma unroll
        for (int off = 16; off; off >>= 1)
            m = fmaxf(m, __shfl_xor_sync(0xffffffffu, m, off));
        float w0 = __expf(s0 - m), w1 = __expf(s1 - m);
        float l = w0 + w1;
        #pragma unroll
        for (int off = 16; off; off >>= 1)
            l += __shfl_xor_sync(0xffffffffu, l, off);
        sW[lid] = w0;
        sW[lid + 32] = w1;
        if (lid == 0) g_mtl[b * NTILES + tile] = make_float2(m, l);
    }
    __syncthreads();

    // ---- ctx partial: cpart[e] = sum_t w[t] * memory[b, t0+t, e] (L2-warm) ----
    {
        const int tmax = min(TTILE, T_ - t0);
        const float* mrow = memory + ((size_t)b * T_ + t0) * E_ + tid * 4;
        float4 acc0 = make_float4(0.f, 0.f, 0.f, 0.f);
        float4 acc1 = make_float4(0.f, 0.f, 0.f, 0.f);
        int t = 0;
        for (; t + 2 <= tmax; t += 2) {
            float w0 = sW[t], w1 = sW[t + 1];
            float4 m0 = *(const float4*)(mrow);
            float4 m1 = *(const float4*)(mrow + E_);
            mrow += 2 * E_;
            acc0.x += w0 * m0.x; acc0.y += w0 * m0.y;
            acc0.z += w0 * m0.z; acc0.w += w0 * m0.w;
            acc1.x += w1 * m1.x; acc1.y += w1 * m1.y;
            acc1.z += w1 * m1.z; acc1.w += w1 * m1.w;
        }
        if (t < tmax) {
            float w0 = sW[t];
            float4 m0 = *(const float4*)(mrow);
            acc0.x += w0 * m0.x; acc0.y += w0 * m0.y;
            acc0.z += w0 * m0.z; acc0.w += w0 * m0.w;
        }
        acc0.x += acc1.x; acc0.y += acc1.y;
        acc0.z += acc1.z; acc0.w += acc1.w;
        *((float4*)(g_cpart + ((size_t)b * NTILES + tile) * E_) + tid) = acc0;
    }
}

// ---------------------------------------------------------------------------
// combine: global softmax over tiles -> context + alignments
// grid (B_, 5): y==0 -> context, y=1..4 -> alignment quarters
// ---------------------------------------------------------------------------
__global__ void combine_kernel(float* __restrict__ ctx_out,
                               float* __restrict__ align_out) {
    __shared__ float fac[NTILES];
    __shared__ float sML[2];
    int b = blockIdx.x, part = blockIdx.y, tid = threadIdx.x;  // 512 threads
    if (tid < NTILES) {
        float2 ml = g_mtl[b * NTILES + tid];
        float M = ml.x;
        #pragma unroll
        for (int off = 16; off; off >>= 1)
            M = fmaxf(M, __shfl_xor_sync(0xffffffffu, M, off));
        float f = __expf(ml.x - M);
        float L = ml.y * f;
        #pragma unroll
        for (int off = 16; off; off >>= 1)
            L += __shfl_xor_sync(0xffffffffu, L, off);
        fac[tid] = f;
        if (tid == 0) { sML[0] = M; sML[1] = L; }
    }
    __syncthreads();
    float M = sML[0];
    float invL = 1.f / sML[1];

    if (part == 0) {
        float s = 0.f;
        #pragma unroll
        for (int i = 0; i < NTILES; ++i)
            s += g_cpart[((size_t)b * NTILES + i) * E_ + tid] * fac[i];
        ctx_out[b * E_ + tid] = s * invL;
    } else {
        int tbeg = (part - 1) * 500;
        for (int t = tbeg + tid; t < tbeg + 500; t += 512)
            align_out[b * T_ + t] = __expf(g_scores[b * T_ + t] - M) * invL;
    }
}

// ---------------------------------------------------------------------------
extern "C" void kernel_launch(void* const* d_in, const int* in_sizes, int n_in,
                              void* d_out, int out_size) {
    const float* query  = (const float*)d_in[0];  // [64,1024]
    const float* memory = (const float*)d_in[1];  // [64,2000,512]
    const float* aw     = (const float*)d_in[2];  // [64,2000,2]
    const float* Wq     = (const float*)d_in[3];  // [128,1024]
    const float* Wm     = (const float*)d_in[4];  // [128,512]
    const float* Wloc   = (const float*)d_in[5];  // [128,2,31]
    const float* v      = (const float*)d_in[6];  // [128]

    float* ctx = (float*)d_out;                   // [64,512]
    float* aligns = ctx + B_ * E_;                // [64,2000]

    cudaFuncSetAttribute(scores_fused_kernel,
                         cudaFuncAttributeMaxDynamicSharedMemorySize, SMEM_TOTAL);

    prep_pq_kernel<<<320, 256>>>(Wm, Wloc, query, Wq);   // launch 0
    dummy_kernel_a<<<1, 32>>>();                         // launch 1
    dummy_kernel_b<<<1, 32>>>();                         // launch 2
    scores_fused_kernel<<<dim3(NTILES, B_), 128, SMEM_TOTAL>>>(memory, aw, v); // 3
    combine_kernel<<<dim3(B_, 5), 512>>>(ctx, aligns);   // launch 4
}